// round 6
// baseline (speedup 1.0000x reference)
#include <cuda_runtime.h>
#include <cuda_bf16.h>
#include <mma.h>
#include <cstdint>

using namespace nvcuda;

constexpr int NWIN = 8, CH = 1024, C2 = 512;
constexpr int SLAB = 256, WINSLABS = 6;
constexpr int ROWS_TOTAL = NWIN * WINSLABS * SLAB;      // 12288
constexpr int GUARD = SLAB;
constexpr int ROWS_ALLOC = ROWS_TOTAL + 2 * GUARD;      // 12800
constexpr int KDIM = 27 * CH;                           // 27648
constexpr int BM = 128, BN = 128, BK = 32;
constexpr int LDA = 48, LDB = 144, LDSTG = 132;
constexpr int SMEM_BYTES = (2 * BM * LDA + 2 * BK * LDB) * 2 * 2; // 86016

__device__ __nv_bfloat16 g_X1h[(size_t)ROWS_ALLOC * CH];
__device__ __nv_bfloat16 g_X1l[(size_t)ROWS_ALLOC * CH];
__device__ __nv_bfloat16 g_X2h[(size_t)ROWS_ALLOC * CH];
__device__ __nv_bfloat16 g_X2l[(size_t)ROWS_ALLOC * CH];
__device__ __nv_bfloat16 g_W1Th[(size_t)KDIM * CH];
__device__ __nv_bfloat16 g_W1Tl[(size_t)KDIM * CH];
__device__ __nv_bfloat16 g_W2Th[(size_t)KDIM * C2];
__device__ __nv_bfloat16 g_W2Tl[(size_t)KDIM * C2];
__device__ float g_pooled[NWIN * C2];
__device__ float g_m1[NWIN * 512];
__device__ float g_m2[NWIN * 512];

__device__ __forceinline__ void split_bf16(float v, __nv_bfloat16& hi, __nv_bfloat16& lo) {
    hi = __float2bfloat16(v);
    lo = __float2bfloat16(v - __bfloat162float(hi));
}

__global__ void k_zero_pooled() {
    int i = blockIdx.x * 256 + threadIdx.x;
    if (i < NWIN * C2) g_pooled[i] = 0.f;
}

// videos (1,8,1024,14,14) -> padded channels-last windows, hi/lo split
__global__ void k_gather(const float* __restrict__ videos) {
    int i = blockIdx.x * 256 + threadIdx.x;
    constexpr int TOT = NWIN * 4 * 14 * 14 * CH;
    if (i >= TOT) return;
    int c = i & (CH - 1);
    int rest = i >> 10;
    int w = rest % 14; rest /= 14;
    int h = rest % 14; rest /= 14;
    int d = rest & 3;
    int t = rest >> 2;
    int frame = t - 4 + d;  // window t holds frames t-4..t-1 (zeros before 0)
    float v = (frame >= 0) ? videos[(size_t)(frame * CH + c) * 196 + h * 14 + w] : 0.f;
    __nv_bfloat16 hi, lo; split_bf16(v, hi, lo);
    size_t dst = (size_t)(GUARD + (t * WINSLABS + d + 1) * SLAB + (h + 1) * 16 + (w + 1)) * CH + c;
    g_X1h[dst] = hi;
    g_X1l[dst] = lo;
}

// conv weights (oc, ic, 27) -> WT[kidx*CH+ic][oc] hi/lo
template<int NOC>
__global__ void k_transpose(const float* __restrict__ w,
                            __nv_bfloat16* __restrict__ wth,
                            __nv_bfloat16* __restrict__ wtl) {
    __shared__ float s[32][28];
    int ocBase = blockIdx.x * 32;
    int ic = blockIdx.y;
    for (int idx = threadIdx.x; idx < 32 * 27; idx += 256) {
        int oc = idx / 27, kk = idx - oc * 27;
        s[oc][kk] = w[((size_t)(ocBase + oc) * CH + ic) * 27 + kk];
    }
    __syncthreads();
    for (int idx = threadIdx.x; idx < 27 * 32; idx += 256) {
        int kk = idx >> 5, oc = idx & 31;
        __nv_bfloat16 hi, lo; split_bf16(s[oc][kk], hi, lo);
        size_t o = ((size_t)kk * CH + ic) * NOC + ocBase + oc;
        wth[o] = hi;
        wtl[o] = lo;
    }
}

// Implicit-conv GEMM, bf16 hi/lo 3-term, 128x128x32 tiles, 8 warps.
template<int N, bool POOL>
__global__ void __launch_bounds__(256)
k_gemm(const float* __restrict__ bias) {
    const __nv_bfloat16* __restrict__ Xh = (POOL ? g_X2h : g_X1h) + (size_t)GUARD * CH;
    const __nv_bfloat16* __restrict__ Xl = (POOL ? g_X2l : g_X1l) + (size_t)GUARD * CH;
    const __nv_bfloat16* __restrict__ Wh = POOL ? g_W2Th : g_W1Th;
    const __nv_bfloat16* __restrict__ Wl = POOL ? g_W2Tl : g_W1Tl;

    extern __shared__ char smem_raw[];
    __nv_bfloat16* Ah = (__nv_bfloat16*)smem_raw;
    __nv_bfloat16* Al = Ah + 2 * BM * LDA;
    __nv_bfloat16* Bh = Al + 2 * BM * LDA;
    __nv_bfloat16* Bl = Bh + 2 * BK * LDB;

    const int tid = threadIdx.x;
    const int mtile = blockIdx.x;            // 0..63
    const int nBase = blockIdx.y * BN;
    const int t = mtile >> 3;
    const int rem = mtile & 7;
    const int dp = (rem >> 1) + 1;           // data slabs 1..4
    const int half = rem & 1;
    const int rowBase = (t * WINSLABS + dp) * SLAB + half * BM;

    wmma::fragment<wmma::accumulator, 16, 16, 16, float> acc[4][2];
#pragma unroll
    for (int i = 0; i < 4; i++)
#pragma unroll
        for (int j = 0; j < 2; j++) wmma::fill_fragment(acc[i][j], 0.f);

    const int warpId = tid >> 5;
    const int warpM = warpId >> 2;  // 0..1 -> 64 rows
    const int warpN = warpId & 3;   // 0..3 -> 32 cols

    auto loadTile = [&](int kt, int buf) {
        const int kidx = kt >> 5;
        const int icBase = (kt & 31) << 5;
        const int kd = kidx / 9, r9 = kidx - kd * 9;
        const int kh = r9 / 3, kw = r9 - kh * 3;
        const long off = (long)(kd - 1) * SLAB + (kh - 1) * 16 + (kw - 1);
        const long rb = (long)(rowBase + off) * CH + icBase;
        __nv_bfloat16* dAh = Ah + buf * BM * LDA;
        __nv_bfloat16* dAl = Al + buf * BM * LDA;
#pragma unroll
        for (int it = 0; it < 2; it++) {
            int v = it * 256 + tid;
            int lr = v >> 2, c8 = (v & 3) << 3;
            *(uint4*)(dAh + lr * LDA + c8) = *(const uint4*)(Xh + rb + (long)lr * CH + c8);
            *(uint4*)(dAl + lr * LDA + c8) = *(const uint4*)(Xl + rb + (long)lr * CH + c8);
        }
        const size_t wb = (size_t)kt * BK * N + nBase;
        __nv_bfloat16* dBh = Bh + buf * BK * LDB;
        __nv_bfloat16* dBl = Bl + buf * BK * LDB;
#pragma unroll
        for (int it = 0; it < 2; it++) {
            int v = it * 256 + tid;
            int row = v >> 4, c8 = (v & 15) << 3;
            *(uint4*)(dBh + row * LDB + c8) = *(const uint4*)(Wh + wb + (size_t)row * N + c8);
            *(uint4*)(dBl + row * LDB + c8) = *(const uint4*)(Wl + wb + (size_t)row * N + c8);
        }
    };

    const int KT = KDIM / BK;  // 864
    loadTile(0, 0);
    __syncthreads();

    for (int kt = 0; kt < KT; kt++) {
        const int cur = kt & 1;
        if (kt + 1 < KT) loadTile(kt + 1, cur ^ 1);
        const __nv_bfloat16* ah = Ah + cur * BM * LDA;
        const __nv_bfloat16* al = Al + cur * BM * LDA;
        const __nv_bfloat16* bh = Bh + cur * BK * LDB;
        const __nv_bfloat16* bl = Bl + cur * BK * LDB;
#pragma unroll
        for (int ks = 0; ks < 2; ks++) {
            wmma::fragment<wmma::matrix_b, 16, 16, 16, __nv_bfloat16, wmma::row_major> fbh[2], fbl[2];
#pragma unroll
            for (int j = 0; j < 2; j++) {
                wmma::load_matrix_sync(fbh[j], bh + ks * 16 * LDB + warpN * 32 + j * 16, LDB);
                wmma::load_matrix_sync(fbl[j], bl + ks * 16 * LDB + warpN * 32 + j * 16, LDB);
            }
#pragma unroll
            for (int i = 0; i < 4; i++) {
                wmma::fragment<wmma::matrix_a, 16, 16, 16, __nv_bfloat16, wmma::row_major> fah, fal;
                wmma::load_matrix_sync(fah, ah + (warpM * 64 + i * 16) * LDA + ks * 16, LDA);
                wmma::load_matrix_sync(fal, al + (warpM * 64 + i * 16) * LDA + ks * 16, LDA);
#pragma unroll
                for (int j = 0; j < 2; j++) {
                    wmma::mma_sync(acc[i][j], fah, fbh[j], acc[i][j]);
                    wmma::mma_sync(acc[i][j], fah, fbl[j], acc[i][j]);
                    wmma::mma_sync(acc[i][j], fal, fbh[j], acc[i][j]);
                }
            }
        }
        __syncthreads();
    }

    // stage accumulators
    float* Stage = (float*)smem_raw;  // 128 x LDSTG floats = 67584 B
#pragma unroll
    for (int i = 0; i < 4; i++)
#pragma unroll
        for (int j = 0; j < 2; j++)
            wmma::store_matrix_sync(Stage + (warpM * 64 + i * 16) * LDSTG + warpN * 32 + j * 16,
                                    acc[i][j], LDSTG, wmma::mem_row_major);
    __syncthreads();

    if (!POOL) {
        // bias + relu + pad-mask -> X2 hi/lo (channels-last)
        const int r = tid & 127, chunk = tid >> 7;       // chunk: 64-col half
        const int sr = half * 128 + r;
        const int hp = sr >> 4, wp = sr & 15;
        const bool valid = (hp >= 1 && hp <= 14 && wp >= 1 && wp <= 14);
        __nv_bfloat16* Yh = g_X2h + ((size_t)(GUARD + rowBase + r)) * CH + nBase + chunk * 64;
        __nv_bfloat16* Yl = g_X2l + ((size_t)(GUARD + rowBase + r)) * CH + nBase + chunk * 64;
        const float* srow = Stage + r * LDSTG + chunk * 64;
        const float* brow = bias + nBase + chunk * 64;
#pragma unroll
        for (int j = 0; j < 8; j++) {
            __nv_bfloat16 ph[8], pl[8];
#pragma unroll
            for (int e = 0; e < 8; e++) {
                float v = valid ? fmaxf(srow[j * 8 + e] + brow[j * 8 + e], 0.f) : 0.f;
                split_bf16(v, ph[e], pl[e]);
            }
            *(uint4*)(Yh + j * 8) = *(uint4*)ph;
            *(uint4*)(Yl + j * 8) = *(uint4*)pl;
        }
    } else {
        // bias + relu + maxpool over valid rows -> atomicMax
        const int col = tid & 127, rh = tid >> 7;
        float m = 0.f;
        for (int r = rh * 64; r < rh * 64 + 64; r++) {
            int sr = half * 128 + r;
            int hp = sr >> 4, wp = sr & 15;
            if (hp >= 1 && hp <= 14 && wp >= 1 && wp <= 14)
                m = fmaxf(m, Stage[r * LDSTG + col] + bias[nBase + col]);
        }
        m = fmaxf(m, 0.f);
        atomicMax((int*)&g_pooled[t * C2 + nBase + col], __float_as_int(m));
    }
}

// y[t,o] = relu(sum_i x[t,i]*W[o,i] + b[o]); warp per (t,o)
template<int IN, int OUT>
__global__ void k_fc(const float* __restrict__ W, const float* __restrict__ b,
                     const float* __restrict__ x, float* __restrict__ y) {
    int w = threadIdx.x >> 5, lane = threadIdx.x & 31;
    int o = blockIdx.x * 8 + w, t = blockIdx.y;
    float s = 0.f;
    for (int i = lane; i < IN; i += 32) s += x[t * IN + i] * W[(size_t)o * IN + i];
#pragma unroll
    for (int d = 16; d; d >>= 1) s += __shfl_down_sync(0xffffffffu, s, d);
    if (lane == 0) y[t * OUT + o] = fmaxf(s + b[o], 0.f);
}

extern "C" void kernel_launch(void* const* d_in, const int* in_sizes, int n_in,
                              void* d_out, int out_size) {
    const float* videos  = (const float*)d_in[0];
    const float* conv1_w = (const float*)d_in[1];
    const float* conv1_b = (const float*)d_in[2];
    const float* conv2_w = (const float*)d_in[3];
    const float* conv2_b = (const float*)d_in[4];
    const float* l1_w = (const float*)d_in[5];
    const float* l1_b = (const float*)d_in[6];
    const float* l2_w = (const float*)d_in[7];
    const float* l2_b = (const float*)d_in[8];
    const float* l3_w = (const float*)d_in[9];
    const float* l3_b = (const float*)d_in[10];
    float* out = (float*)d_out;

    cudaFuncSetAttribute(k_gemm<CH, false>, cudaFuncAttributeMaxDynamicSharedMemorySize, SMEM_BYTES);
    cudaFuncSetAttribute(k_gemm<C2, true>, cudaFuncAttributeMaxDynamicSharedMemorySize, SMEM_BYTES);

    __nv_bfloat16 *w1th, *w1tl, *w2th, *w2tl;
    float *pooled, *m1, *m2;
    cudaGetSymbolAddress((void**)&w1th, g_W1Th);
    cudaGetSymbolAddress((void**)&w1tl, g_W1Tl);
    cudaGetSymbolAddress((void**)&w2th, g_W2Th);
    cudaGetSymbolAddress((void**)&w2tl, g_W2Tl);
    cudaGetSymbolAddress((void**)&pooled, g_pooled);
    cudaGetSymbolAddress((void**)&m1, g_m1);
    cudaGetSymbolAddress((void**)&m2, g_m2);

    constexpr int TOT = NWIN * 4 * 14 * 14 * CH;
    k_gather<<<(TOT + 255) / 256, 256>>>(videos);
    k_transpose<CH><<<dim3(CH / 32, CH), 256>>>(conv1_w, w1th, w1tl);
    k_transpose<C2><<<dim3(C2 / 32, CH), 256>>>(conv2_w, w2th, w2tl);
    k_zero_pooled<<<(NWIN * C2 + 255) / 256, 256>>>();

    k_gemm<CH, false><<<dim3(64, CH / BN), 256, SMEM_BYTES>>>(conv1_b);
    k_gemm<C2, true><<<dim3(64, C2 / BN), 256, SMEM_BYTES>>>(conv2_b);

    k_fc<512, 512><<<dim3(64, NWIN), 256>>>(l1_w, l1_b, pooled, m1);
    k_fc<512, 512><<<dim3(64, NWIN), 256>>>(l2_w, l2_b, m1, m2);
    k_fc<512, 128><<<dim3(16, NWIN), 256>>>(l3_w, l3_b, m2, out);
}

// round 8
// speedup vs baseline: 1.6536x; 1.6536x over previous
#include <cuda_runtime.h>
#include <cuda_bf16.h>
#include <mma.h>
#include <cstdint>

using namespace nvcuda;

constexpr int NWIN = 8, CH = 1024, C2 = 512;
constexpr int SLAB = 256, WINSLABS = 6, GUARD = 256;
constexpr int ROWS_ALLOC = NWIN * WINSLABS * SLAB + 2 * GUARD;  // 12800
constexpr int KDIM = 27 * CH;                                    // 27648
constexpr int BM = 128, BN = 128, BK = 32;
constexpr int KT = KDIM / BK;                                    // 864

// smem strides chosen so ldmatrix row-sets are bank-conflict-free:
// byte stride mod 32 banks == 4 mod 8 banks -> stride bytes ≡ 16 (mod 32)
constexpr int LDA = 40;    // elements: 80 B rows for 32-bf16 A tile rows
constexpr int LDB = 136;   // elements: 272 B rows for 128-bf16 B tile rows
constexpr int LDSTG = 132; // fp32 epilogue staging stride

constexpr int A_BUF = BM * LDA * 2;   // 10240 B per A tile buffer
constexpr int B_BUF = BK * LDB * 2;   // 8704 B per B tile buffer
constexpr int OFF_AH = 0;
constexpr int OFF_AL = 2 * A_BUF;             // 20480
constexpr int OFF_BH = 4 * A_BUF;             // 40960
constexpr int OFF_BL = OFF_BH + 2 * B_BUF;    // 58368
constexpr int SMEM_BYTES = OFF_BL + 2 * B_BUF; // 75776  (2 CTAs/SM fit)

__device__ __nv_bfloat16 g_X1h[(size_t)ROWS_ALLOC * CH];
__device__ __nv_bfloat16 g_X1l[(size_t)ROWS_ALLOC * CH];
__device__ __nv_bfloat16 g_X2h[(size_t)ROWS_ALLOC * CH];
__device__ __nv_bfloat16 g_X2l[(size_t)ROWS_ALLOC * CH];
__device__ __nv_bfloat16 g_W1Th[(size_t)KDIM * CH];   // [kidx*CH+ic][oc]
__device__ __nv_bfloat16 g_W1Tl[(size_t)KDIM * CH];
__device__ __nv_bfloat16 g_W2Th[(size_t)KDIM * C2];
__device__ __nv_bfloat16 g_W2Tl[(size_t)KDIM * C2];
__device__ float g_pooled[NWIN * C2];
__device__ float g_m1[NWIN * 512];
__device__ float g_m2[NWIN * 512];

__device__ __forceinline__ void split_bf16(float v, __nv_bfloat16& hi, __nv_bfloat16& lo) {
    hi = __float2bfloat16(v);
    lo = __float2bfloat16(v - __bfloat162float(hi));
}

__device__ __forceinline__ uint32_t smem_u32(const void* p) {
    uint32_t a;
    asm("{ .reg .u64 t; cvta.to.shared.u64 t, %1; cvt.u32.u64 %0, t; }" : "=r"(a) : "l"(p));
    return a;
}
#define CP_ASYNC16(dst, src) \
    asm volatile("cp.async.cg.shared.global [%0], [%1], 16;" :: "r"(dst), "l"(src))
#define CP_COMMIT() asm volatile("cp.async.commit_group;" ::: "memory")
#define CP_WAIT0()  asm volatile("cp.async.wait_group 0;" ::: "memory")

// ---------------- prep kernels ----------------
__global__ void k_zero_pooled() {
    int i = blockIdx.x * 256 + threadIdx.x;
    if (i < NWIN * C2) g_pooled[i] = 0.f;
}

// videos (1,8,1024,14,14) -> padded channels-last windows, hi/lo split
__global__ void k_gather(const float* __restrict__ videos) {
    int i = blockIdx.x * 256 + threadIdx.x;
    constexpr int TOT = NWIN * 4 * 14 * 14 * CH;
    if (i >= TOT) return;
    int c = i & (CH - 1);
    int rest = i >> 10;
    int w = rest % 14; rest /= 14;
    int h = rest % 14; rest /= 14;
    int d = rest & 3;
    int t = rest >> 2;
    int frame = t - 4 + d;  // window t holds frames t-4..t-1 (zeros before 0)
    float v = (frame >= 0) ? videos[(size_t)(frame * CH + c) * 196 + h * 14 + w] : 0.f;
    __nv_bfloat16 hi, lo; split_bf16(v, hi, lo);
    size_t dst = (size_t)(GUARD + (t * WINSLABS + d + 1) * SLAB + (h + 1) * 16 + (w + 1)) * CH + c;
    g_X1h[dst] = hi;
    g_X1l[dst] = lo;
}

// conv weights (oc, ic, 27) -> WT[kidx*CH+ic][oc] hi/lo
template<int NOC>
__global__ void k_transpose(const float* __restrict__ w,
                            __nv_bfloat16* __restrict__ wth,
                            __nv_bfloat16* __restrict__ wtl) {
    __shared__ float s[32][28];
    int ocBase = blockIdx.x * 32;
    int ic = blockIdx.y;
    for (int idx = threadIdx.x; idx < 32 * 27; idx += 256) {
        int oc = idx / 27, kk = idx - oc * 27;
        s[oc][kk] = w[((size_t)(ocBase + oc) * CH + ic) * 27 + kk];
    }
    __syncthreads();
    for (int idx = threadIdx.x; idx < 27 * 32; idx += 256) {
        int kk = idx >> 5, oc = idx & 31;
        __nv_bfloat16 hi, lo; split_bf16(s[oc][kk], hi, lo);
        size_t o = ((size_t)kk * CH + ic) * NOC + ocBase + oc;
        wth[o] = hi;
        wtl[o] = lo;
    }
}

// ---------- implicit-conv GEMM: bf16 hi/lo 3-term, cp.async pipeline ----------
template<int N, bool POOL>
__global__ void __launch_bounds__(256, 2)
k_gemm(const float* __restrict__ bias) {
    const __nv_bfloat16* __restrict__ Xh = (POOL ? g_X2h : g_X1h) + (size_t)GUARD * CH;
    const __nv_bfloat16* __restrict__ Xl = (POOL ? g_X2l : g_X1l) + (size_t)GUARD * CH;
    const __nv_bfloat16* __restrict__ Wh = POOL ? g_W2Th : g_W1Th;
    const __nv_bfloat16* __restrict__ Wl = POOL ? g_W2Tl : g_W1Tl;

    extern __shared__ __align__(128) char smem_raw[];
    const uint32_t sbase = smem_u32(smem_raw);

    const int tid = threadIdx.x;
    const int mtile = blockIdx.x;            // 0..63
    const int nBase = blockIdx.y * BN;
    const int t = mtile >> 3;
    const int rem = mtile & 7;
    const int dp = (rem >> 1) + 1;           // data slabs 1..4
    const int half = rem & 1;
    const int rowBase = (t * WINSLABS + dp) * SLAB + half * BM;

    wmma::fragment<wmma::accumulator, 16, 16, 16, float> acc[4][2];
#pragma unroll
    for (int i = 0; i < 4; i++)
#pragma unroll
        for (int j = 0; j < 2; j++) wmma::fill_fragment(acc[i][j], 0.f);

    const int warpId = tid >> 5;
    const int warpM = warpId >> 2;  // 0..1 -> 64 rows
    const int warpN = warpId & 3;   // 0..3 -> 32 cols

    // cp.async fill of one K-chunk (A: 128x32, B: 32xN-slice of 128), hi+lo
    auto loadTile = [&](int kt, int buf) {
        const int kidx = kt >> 5;            // tap 0..26
        const int icBase = (kt & 31) << 5;
        const int kd = kidx / 9, r9 = kidx - kd * 9;
        const int kh = r9 / 3, kw = r9 - kh * 3;
        const long off = (long)(kd - 1) * SLAB + (kh - 1) * 16 + (kw - 1);
        const long rb = (long)(rowBase + off) * CH + icBase;
        const uint32_t aH = sbase + OFF_AH + buf * A_BUF;
        const uint32_t aL = sbase + OFF_AL + buf * A_BUF;
#pragma unroll
        for (int it = 0; it < 2; it++) {
            int v = it * 256 + tid;          // 512 chunks: 128 rows x 4 x 16B
            int row = v >> 2, c = v & 3;
            long so = rb + (long)row * CH + c * 8;
            uint32_t do_ = row * (LDA * 2) + c * 16;
            CP_ASYNC16(aH + do_, Xh + so);
            CP_ASYNC16(aL + do_, Xl + so);
        }
        const size_t wb = (size_t)kt * BK * N + nBase;
        const uint32_t bH = sbase + OFF_BH + buf * B_BUF;
        const uint32_t bL = sbase + OFF_BL + buf * B_BUF;
#pragma unroll
        for (int it = 0; it < 2; it++) {
            int v = it * 256 + tid;          // 512 chunks: 32 rows x 16 x 16B
            int row = v >> 4, c = v & 15;
            size_t so = wb + (size_t)row * N + c * 8;
            uint32_t do_ = row * (LDB * 2) + c * 16;
            CP_ASYNC16(bH + do_, Wh + so);
            CP_ASYNC16(bL + do_, Wl + so);
        }
    };

    loadTile(0, 0);
    CP_COMMIT();

    for (int kt = 0; kt < KT; kt++) {
        const int buf = kt & 1;
        CP_WAIT0();
        __syncthreads();                 // buf tile fully resident for all threads
        if (kt + 1 < KT) {               // prefetch next into buf^1 (readers done last iter)
            loadTile(kt + 1, buf ^ 1);
            CP_COMMIT();
        }
        const __nv_bfloat16* ah = (const __nv_bfloat16*)(smem_raw + OFF_AH + buf * A_BUF);
        const __nv_bfloat16* al = (const __nv_bfloat16*)(smem_raw + OFF_AL + buf * A_BUF);
        const __nv_bfloat16* bh = (const __nv_bfloat16*)(smem_raw + OFF_BH + buf * B_BUF);
        const __nv_bfloat16* bl = (const __nv_bfloat16*)(smem_raw + OFF_BL + buf * B_BUF);
#pragma unroll
        for (int ks = 0; ks < 2; ks++) {
            wmma::fragment<wmma::matrix_b, 16, 16, 16, __nv_bfloat16, wmma::row_major> fbh[2], fbl[2];
#pragma unroll
            for (int j = 0; j < 2; j++) {
                wmma::load_matrix_sync(fbh[j], bh + ks * 16 * LDB + warpN * 32 + j * 16, LDB);
                wmma::load_matrix_sync(fbl[j], bl + ks * 16 * LDB + warpN * 32 + j * 16, LDB);
            }
#pragma unroll
            for (int i = 0; i < 4; i++) {
                wmma::fragment<wmma::matrix_a, 16, 16, 16, __nv_bfloat16, wmma::row_major> fah, fal;
                wmma::load_matrix_sync(fah, ah + (warpM * 64 + i * 16) * LDA + ks * 16, LDA);
                wmma::load_matrix_sync(fal, al + (warpM * 64 + i * 16) * LDA + ks * 16, LDA);
#pragma unroll
                for (int j = 0; j < 2; j++) {
                    wmma::mma_sync(acc[i][j], fah, fbh[j], acc[i][j]);
                    wmma::mma_sync(acc[i][j], fah, fbl[j], acc[i][j]);
                    wmma::mma_sync(acc[i][j], fal, fbh[j], acc[i][j]);
                }
            }
        }
        __syncthreads();                 // readers of buf done before it is refilled (kt+2)
    }

    // ---------------- epilogue (staged through smem) ----------------
    float* Stage = (float*)smem_raw;     // 128 x LDSTG fp32 = 67584 B <= 75776
#pragma unroll
    for (int i = 0; i < 4; i++)
#pragma unroll
        for (int j = 0; j < 2; j++)
            wmma::store_matrix_sync(Stage + (warpM * 64 + i * 16) * LDSTG + warpN * 32 + j * 16,
                                    acc[i][j], LDSTG, wmma::mem_row_major);
    __syncthreads();

    if (!POOL) {
        const int r = tid & 127, chunk = tid >> 7;
        const int sr = half * 128 + r;
        const int hp = sr >> 4, wp = sr & 15;
        const bool valid = (hp >= 1 && hp <= 14 && wp >= 1 && wp <= 14);
        __nv_bfloat16* Yh = g_X2h + (size_t)(GUARD + rowBase + r) * CH + nBase + chunk * 64;
        __nv_bfloat16* Yl = g_X2l + (size_t)(GUARD + rowBase + r) * CH + nBase + chunk * 64;
        const float* srow = Stage + r * LDSTG + chunk * 64;
        const float* brow = bias + nBase + chunk * 64;
#pragma unroll
        for (int j = 0; j < 8; j++) {
            __nv_bfloat16 ph[8], pl[8];
#pragma unroll
            for (int e = 0; e < 8; e++) {
                float v = valid ? fmaxf(srow[j * 8 + e] + brow[j * 8 + e], 0.f) : 0.f;
                split_bf16(v, ph[e], pl[e]);
            }
            *(uint4*)(Yh + j * 8) = *(uint4*)ph;
            *(uint4*)(Yl + j * 8) = *(uint4*)pl;
        }
    } else {
        const int col = tid & 127, rh = tid >> 7;
        float m = 0.f;
        for (int r = rh * 64; r < rh * 64 + 64; r++) {
            int sr = half * 128 + r;
            int hp = sr >> 4, wp = sr & 15;
            if (hp >= 1 && hp <= 14 && wp >= 1 && wp <= 14)
                m = fmaxf(m, Stage[r * LDSTG + col] + bias[nBase + col]);
        }
        m = fmaxf(m, 0.f);
        atomicMax((int*)&g_pooled[t * C2 + nBase + col], __float_as_int(m));
    }
}

// ---------------- tiny MLP ----------------
template<int IN, int OUT>
__global__ void k_fc(const float* __restrict__ W, const float* __restrict__ b,
                     const float* __restrict__ x, float* __restrict__ y) {
    int w = threadIdx.x >> 5, lane = threadIdx.x & 31;
    int o = blockIdx.x * 8 + w, t = blockIdx.y;
    float s = 0.f;
    for (int i = lane; i < IN; i += 32) s += x[t * IN + i] * W[(size_t)o * IN + i];
#pragma unroll
    for (int d = 16; d; d >>= 1) s += __shfl_down_sync(0xffffffffu, s, d);
    if (lane == 0) y[t * OUT + o] = fmaxf(s + b[o], 0.f);
}

extern "C" void kernel_launch(void* const* d_in, const int* in_sizes, int n_in,
                              void* d_out, int out_size) {
    const float* videos  = (const float*)d_in[0];
    const float* conv1_w = (const float*)d_in[1];
    const float* conv1_b = (const float*)d_in[2];
    const float* conv2_w = (const float*)d_in[3];
    const float* conv2_b = (const float*)d_in[4];
    const float* l1_w = (const float*)d_in[5];
    const float* l1_b = (const float*)d_in[6];
    const float* l2_w = (const float*)d_in[7];
    const float* l2_b = (const float*)d_in[8];
    const float* l3_w = (const float*)d_in[9];
    const float* l3_b = (const float*)d_in[10];
    float* out = (float*)d_out;

    cudaFuncSetAttribute(k_gemm<CH, false>, cudaFuncAttributeMaxDynamicSharedMemorySize, SMEM_BYTES);
    cudaFuncSetAttribute(k_gemm<C2, true>,  cudaFuncAttributeMaxDynamicSharedMemorySize, SMEM_BYTES);

    __nv_bfloat16 *w1th, *w1tl, *w2th, *w2tl;
    float *pooled, *m1, *m2;
    cudaGetSymbolAddress((void**)&w1th, g_W1Th);
    cudaGetSymbolAddress((void**)&w1tl, g_W1Tl);
    cudaGetSymbolAddress((void**)&w2th, g_W2Th);
    cudaGetSymbolAddress((void**)&w2tl, g_W2Tl);
    cudaGetSymbolAddress((void**)&pooled, g_pooled);
    cudaGetSymbolAddress((void**)&m1, g_m1);
    cudaGetSymbolAddress((void**)&m2, g_m2);

    constexpr int TOT = NWIN * 4 * 14 * 14 * CH;
    k_gather<<<(TOT + 255) / 256, 256>>>(videos);
    k_transpose<CH><<<dim3(CH / 32, CH), 256>>>(conv1_w, w1th, w1tl);
    k_transpose<C2><<<dim3(C2 / 32, CH), 256>>>(conv2_w, w2th, w2tl);
    k_zero_pooled<<<(NWIN * C2 + 255) / 256, 256>>>();

    k_gemm<CH, false><<<dim3(64, CH / BN), 256, SMEM_BYTES>>>(conv1_b);
    k_gemm<C2, true><<<dim3(64, C2 / BN), 256, SMEM_BYTES>>>(conv2_b);

    k_fc<512, 512><<<dim3(64, NWIN), 256>>>(l1_w, l1_b, pooled, m1);
    k_fc<512, 512><<<dim3(64, NWIN), 256>>>(l2_w, l2_b, m1, m2);
    k_fc<512, 128><<<dim3(16, NWIN), 256>>>(l3_w, l3_b, m2, out);
}

// round 9
// speedup vs baseline: 2.4070x; 1.4556x over previous
#include <cuda_runtime.h>
#include <cuda_bf16.h>
#include <mma.h>
#include <cstdint>

using namespace nvcuda;

constexpr int NWIN = 8, CH = 1024, C2 = 512;
constexpr int SLAB = 256, WINSLABS = 6, GUARD = 256;
constexpr int ROWS_ALLOC = NWIN * WINSLABS * SLAB + 2 * GUARD;  // 12800
constexpr int KDIM = 27 * CH;                                    // 27648
constexpr int BM = 128, BN = 128, BK = 32;

constexpr int VROWS = NWIN * 4 * 196;   // 6272 valid output rows
constexpr int NMT = VROWS / BM;         // 49 m-tiles (exact)
constexpr int SPLITS = 3;
constexpr int KCH = KDIM / BK / SPLITS; // 288 chunks per split (9 taps)

// bank-conflict-free smem strides (bytes ≡ 16 mod 32)
constexpr int LDA = 40;    // elements
constexpr int LDB = 136;   // elements
constexpr int LDSTG = 132; // fp32 staging stride

constexpr int A_BUF = BM * LDA * 2;   // 10240 B
constexpr int B_BUF = BK * LDB * 2;   // 8704 B
constexpr int OFF_AH = 0;
constexpr int OFF_AL = 2 * A_BUF;
constexpr int OFF_BH = 4 * A_BUF;
constexpr int OFF_BL = OFF_BH + 2 * B_BUF;
constexpr int SMEM_BYTES = OFF_BL + 2 * B_BUF;  // 75776

__device__ __nv_bfloat16 g_X1h[(size_t)ROWS_ALLOC * CH];
__device__ __nv_bfloat16 g_X1l[(size_t)ROWS_ALLOC * CH];
__device__ __nv_bfloat16 g_X2h[(size_t)ROWS_ALLOC * CH];
__device__ __nv_bfloat16 g_X2l[(size_t)ROWS_ALLOC * CH];
__device__ __nv_bfloat16 g_W1Th[(size_t)KDIM * CH];   // [kidx*CH+ic][oc]
__device__ __nv_bfloat16 g_W1Tl[(size_t)KDIM * CH];
__device__ __nv_bfloat16 g_W2Th[(size_t)KDIM * C2];
__device__ __nv_bfloat16 g_W2Tl[(size_t)KDIM * C2];
__device__ float g_part[(size_t)SPLITS * NMT * 8 * BM * BN];  // 77 MB fp32 partials
__device__ float g_pooled[NWIN * C2];
__device__ float g_m1[NWIN * 512];
__device__ float g_m2[NWIN * 512];

__device__ __forceinline__ void split_bf16(float v, __nv_bfloat16& hi, __nv_bfloat16& lo) {
    hi = __float2bfloat16(v);
    lo = __float2bfloat16(v - __bfloat162float(hi));
}

// valid-row index -> padded row in X layout
__device__ __forceinline__ int padded_row(int i) {
    int t = i / 784, rem = i - t * 784;
    int d = rem / 196, s = rem - d * 196;
    int h = s / 14, w = s - h * 14;
    return (t * WINSLABS + d + 1) * SLAB + (h + 1) * 16 + (w + 1);
}

__device__ __forceinline__ uint32_t smem_u32(const void* p) {
    uint32_t a;
    asm("{ .reg .u64 t; cvta.to.shared.u64 t, %1; cvt.u32.u64 %0, t; }" : "=r"(a) : "l"(p));
    return a;
}
#define CP_ASYNC16(dst, src) \
    asm volatile("cp.async.cg.shared.global [%0], [%1], 16;" :: "r"(dst), "l"(src))
#define CP_COMMIT() asm volatile("cp.async.commit_group;" ::: "memory")
#define CP_WAIT0()  asm volatile("cp.async.wait_group 0;" ::: "memory")

// ---------------- prep kernels ----------------
__global__ void k_zero_pooled() {
    int i = blockIdx.x * 256 + threadIdx.x;
    if (i < NWIN * C2) g_pooled[i] = 0.f;
}

__global__ void k_gather(const float* __restrict__ videos) {
    int i = blockIdx.x * 256 + threadIdx.x;
    constexpr int TOT = NWIN * 4 * 14 * 14 * CH;
    if (i >= TOT) return;
    int c = i & (CH - 1);
    int rest = i >> 10;
    int w = rest % 14; rest /= 14;
    int h = rest % 14; rest /= 14;
    int d = rest & 3;
    int t = rest >> 2;
    int frame = t - 4 + d;  // window t holds frames t-4..t-1 (zeros before 0)
    float v = (frame >= 0) ? videos[(size_t)(frame * CH + c) * 196 + h * 14 + w] : 0.f;
    __nv_bfloat16 hi, lo; split_bf16(v, hi, lo);
    size_t dst = (size_t)(GUARD + (t * WINSLABS + d + 1) * SLAB + (h + 1) * 16 + (w + 1)) * CH + c;
    g_X1h[dst] = hi;
    g_X1l[dst] = lo;
}

template<int NOC>
__global__ void k_transpose(const float* __restrict__ w,
                            __nv_bfloat16* __restrict__ wth,
                            __nv_bfloat16* __restrict__ wtl) {
    __shared__ float s[32][28];
    int ocBase = blockIdx.x * 32;
    int ic = blockIdx.y;
    for (int idx = threadIdx.x; idx < 32 * 27; idx += 256) {
        int oc = idx / 27, kk = idx - oc * 27;
        s[oc][kk] = w[((size_t)(ocBase + oc) * CH + ic) * 27 + kk];
    }
    __syncthreads();
    for (int idx = threadIdx.x; idx < 27 * 32; idx += 256) {
        int kk = idx >> 5, oc = idx & 31;
        __nv_bfloat16 hi, lo; split_bf16(s[oc][kk], hi, lo);
        size_t o = ((size_t)kk * CH + ic) * NOC + ocBase + oc;
        wth[o] = hi;
        wtl[o] = lo;
    }
}

// ---------- implicit-conv GEMM: compacted M, split-K, fp32 partial out ----------
template<int N, bool L2>
__global__ void __launch_bounds__(256, 2)
k_gemm(int dummy) {
    const __nv_bfloat16* __restrict__ Xh = (L2 ? g_X2h : g_X1h) + (size_t)GUARD * CH;
    const __nv_bfloat16* __restrict__ Xl = (L2 ? g_X2l : g_X1l) + (size_t)GUARD * CH;
    const __nv_bfloat16* __restrict__ Wh = L2 ? g_W2Th : g_W1Th;
    const __nv_bfloat16* __restrict__ Wl = L2 ? g_W2Tl : g_W1Tl;

    extern __shared__ __align__(128) char smem_raw[];
    const uint32_t sbase = smem_u32(smem_raw);

    const int tid = threadIdx.x;
    const int mtile = blockIdx.x;          // 0..48
    const int nBase = blockIdx.y * BN;
    const int split = blockIdx.z;          // 0..2
    const int k0 = split * KCH;            // chunk base

    // per-thread A source rows (fixed across K loop)
    const int r0 = tid >> 2;
    const long pr0 = padded_row(mtile * BM + r0);
    const long pr1 = padded_row(mtile * BM + r0 + 64);
    const int ac = (tid & 3) * 8;          // A column element offset (16B units)

    wmma::fragment<wmma::accumulator, 16, 16, 16, float> acc[4][2];
#pragma unroll
    for (int i = 0; i < 4; i++)
#pragma unroll
        for (int j = 0; j < 2; j++) wmma::fill_fragment(acc[i][j], 0.f);

    const int warpId = tid >> 5;
    const int warpM = warpId >> 2;
    const int warpN = warpId & 3;

    auto loadTile = [&](int kt, int buf) {
        const int kidx = kt >> 5;
        const int icBase = (kt & 31) << 5;
        const int kd = kidx / 9, r9 = kidx - kd * 9;
        const int kh = r9 / 3, kw = r9 - kh * 3;
        const long off = (long)(kd - 1) * SLAB + (kh - 1) * 16 + (kw - 1);
        const uint32_t aH = sbase + OFF_AH + buf * A_BUF;
        const uint32_t aL = sbase + OFF_AL + buf * A_BUF;
#pragma unroll
        for (int it = 0; it < 2; it++) {
            const long so = ((it ? pr1 : pr0) + off) * CH + icBase + ac;
            const uint32_t do_ = (r0 + it * 64) * (LDA * 2) + (ac * 2);
            CP_ASYNC16(aH + do_, Xh + so);
            CP_ASYNC16(aL + do_, Xl + so);
        }
        const size_t wb = (size_t)kt * BK * N + nBase;
        const uint32_t bH = sbase + OFF_BH + buf * B_BUF;
        const uint32_t bL = sbase + OFF_BL + buf * B_BUF;
#pragma unroll
        for (int it = 0; it < 2; it++) {
            int v = it * 256 + tid;
            int row = v >> 4, c = v & 15;
            size_t so = wb + (size_t)row * N + c * 8;
            uint32_t do_ = row * (LDB * 2) + c * 16;
            CP_ASYNC16(bH + do_, Wh + so);
            CP_ASYNC16(bL + do_, Wl + so);
        }
    };

    loadTile(k0, 0);
    CP_COMMIT();

    for (int kk = 0; kk < KCH; kk++) {
        const int buf = kk & 1;
        CP_WAIT0();
        __syncthreads();
        if (kk + 1 < KCH) {
            loadTile(k0 + kk + 1, buf ^ 1);
            CP_COMMIT();
        }
        const __nv_bfloat16* ah = (const __nv_bfloat16*)(smem_raw + OFF_AH + buf * A_BUF);
        const __nv_bfloat16* al = (const __nv_bfloat16*)(smem_raw + OFF_AL + buf * A_BUF);
        const __nv_bfloat16* bh = (const __nv_bfloat16*)(smem_raw + OFF_BH + buf * B_BUF);
        const __nv_bfloat16* bl = (const __nv_bfloat16*)(smem_raw + OFF_BL + buf * B_BUF);
#pragma unroll
        for (int ks = 0; ks < 2; ks++) {
            wmma::fragment<wmma::matrix_b, 16, 16, 16, __nv_bfloat16, wmma::row_major> fbh[2], fbl[2];
#pragma unroll
            for (int j = 0; j < 2; j++) {
                wmma::load_matrix_sync(fbh[j], bh + ks * 16 * LDB + warpN * 32 + j * 16, LDB);
                wmma::load_matrix_sync(fbl[j], bl + ks * 16 * LDB + warpN * 32 + j * 16, LDB);
            }
#pragma unroll
            for (int i = 0; i < 4; i++) {
                wmma::fragment<wmma::matrix_a, 16, 16, 16, __nv_bfloat16, wmma::row_major> fah, fal;
                wmma::load_matrix_sync(fah, ah + (warpM * 64 + i * 16) * LDA + ks * 16, LDA);
                wmma::load_matrix_sync(fal, al + (warpM * 64 + i * 16) * LDA + ks * 16, LDA);
#pragma unroll
                for (int j = 0; j < 2; j++) {
                    wmma::mma_sync(acc[i][j], fah, fbh[j], acc[i][j]);
                    wmma::mma_sync(acc[i][j], fah, fbl[j], acc[i][j]);
                    wmma::mma_sync(acc[i][j], fal, fbh[j], acc[i][j]);
                }
            }
        }
        __syncthreads();
    }

    // stage + coalesced fp32 partial store
    float* Stage = (float*)smem_raw;
#pragma unroll
    for (int i = 0; i < 4; i++)
#pragma unroll
        for (int j = 0; j < 2; j++)
            wmma::store_matrix_sync(Stage + (warpM * 64 + i * 16) * LDSTG + warpN * 32 + j * 16,
                                    acc[i][j], LDSTG, wmma::mem_row_major);
    __syncthreads();

    float* dst = g_part + ((size_t)(split * NMT + mtile) * 8 + blockIdx.y) * (BM * BN);
#pragma unroll
    for (int it = 0; it < 16; it++) {
        int v = it * 256 + tid;              // 4096 float4
        int row = v >> 5, c4 = (v & 31) * 4;
        *(float4*)(dst + row * BN + c4) = *(const float4*)(Stage + row * LDSTG + c4);
    }
}

// sum 3 partials + bias + relu -> X2 hi/lo at padded rows
__global__ void k_epi1(const float* __restrict__ bias) {
    const int mtile = blockIdx.x, nblk = blockIdx.y;
    const int col = threadIdx.x & 127, rh = threadIdx.x >> 7;
    const size_t tb = ((size_t)mtile * 8 + nblk) * (BM * BN);
    const float* P0 = g_part + tb;
    const float* P1 = g_part + (size_t)NMT * 8 * BM * BN + tb;
    const float* P2 = g_part + (size_t)2 * NMT * 8 * BM * BN + tb;
    const float b = bias[nblk * 128 + col];
    for (int rr = rh * 64; rr < rh * 64 + 64; rr++) {
        int e = rr * BN + col;
        float v = fmaxf(P0[e] + P1[e] + P2[e] + b, 0.f);
        __nv_bfloat16 hi, lo; split_bf16(v, hi, lo);
        size_t o = (size_t)(GUARD + padded_row(mtile * BM + rr)) * CH + nblk * 128 + col;
        g_X2h[o] = hi;
        g_X2l[o] = lo;
    }
}

// sum 3 partials + bias + relu + maxpool -> g_pooled
__global__ void k_epi2(const float* __restrict__ bias) {
    const int mtile = blockIdx.x, nblk = blockIdx.y;
    const int col = threadIdx.x;  // 128 threads
    const size_t tb = ((size_t)mtile * 8 + nblk) * (BM * BN);
    const float* P0 = g_part + tb;
    const float* P1 = g_part + (size_t)NMT * 8 * BM * BN + tb;
    const float* P2 = g_part + (size_t)2 * NMT * 8 * BM * BN + tb;
    const float b = bias[nblk * 128 + col];
    float m = 0.f;
    int curt = (mtile * BM) / 784;
    for (int rr = 0; rr < BM; rr++) {
        int t = (mtile * BM + rr) / 784;
        if (t != curt) {
            atomicMax((int*)&g_pooled[curt * C2 + nblk * 128 + col], __float_as_int(m));
            m = 0.f;
            curt = t;
        }
        int e = rr * BN + col;
        m = fmaxf(m, P0[e] + P1[e] + P2[e] + b);
    }
    atomicMax((int*)&g_pooled[curt * C2 + nblk * 128 + col], __float_as_int(m));
}

// ---------------- tiny MLP ----------------
template<int IN, int OUT>
__global__ void k_fc(const float* __restrict__ W, const float* __restrict__ b,
                     const float* __restrict__ x, float* __restrict__ y) {
    int w = threadIdx.x >> 5, lane = threadIdx.x & 31;
    int o = blockIdx.x * 8 + w, t = blockIdx.y;
    float s = 0.f;
    for (int i = lane; i < IN; i += 32) s += x[t * IN + i] * W[(size_t)o * IN + i];
#pragma unroll
    for (int d = 16; d; d >>= 1) s += __shfl_down_sync(0xffffffffu, s, d);
    if (lane == 0) y[t * OUT + o] = fmaxf(s + b[o], 0.f);
}

extern "C" void kernel_launch(void* const* d_in, const int* in_sizes, int n_in,
                              void* d_out, int out_size) {
    const float* videos  = (const float*)d_in[0];
    const float* conv1_w = (const float*)d_in[1];
    const float* conv1_b = (const float*)d_in[2];
    const float* conv2_w = (const float*)d_in[3];
    const float* conv2_b = (const float*)d_in[4];
    const float* l1_w = (const float*)d_in[5];
    const float* l1_b = (const float*)d_in[6];
    const float* l2_w = (const float*)d_in[7];
    const float* l2_b = (const float*)d_in[8];
    const float* l3_w = (const float*)d_in[9];
    const float* l3_b = (const float*)d_in[10];
    float* out = (float*)d_out;

    cudaFuncSetAttribute(k_gemm<CH, false>, cudaFuncAttributeMaxDynamicSharedMemorySize, SMEM_BYTES);
    cudaFuncSetAttribute(k_gemm<C2, true>,  cudaFuncAttributeMaxDynamicSharedMemorySize, SMEM_BYTES);

    __nv_bfloat16 *w1th, *w1tl, *w2th, *w2tl;
    float *pooled, *m1, *m2;
    cudaGetSymbolAddress((void**)&w1th, g_W1Th);
    cudaGetSymbolAddress((void**)&w1tl, g_W1Tl);
    cudaGetSymbolAddress((void**)&w2th, g_W2Th);
    cudaGetSymbolAddress((void**)&w2tl, g_W2Tl);
    cudaGetSymbolAddress((void**)&pooled, g_pooled);
    cudaGetSymbolAddress((void**)&m1, g_m1);
    cudaGetSymbolAddress((void**)&m2, g_m2);

    constexpr int TOT = NWIN * 4 * 14 * 14 * CH;
    k_gather<<<(TOT + 255) / 256, 256>>>(videos);
    k_transpose<CH><<<dim3(CH / 32, CH), 256>>>(conv1_w, w1th, w1tl);
    k_transpose<C2><<<dim3(C2 / 32, CH), 256>>>(conv2_w, w2th, w2tl);
    k_zero_pooled<<<(NWIN * C2 + 255) / 256, 256>>>();

    k_gemm<CH, false><<<dim3(NMT, CH / BN, SPLITS), 256, SMEM_BYTES>>>(0);
    k_epi1<<<dim3(NMT, CH / BN), 256>>>(conv1_b);

    k_gemm<C2, true><<<dim3(NMT, C2 / BN, SPLITS), 256, SMEM_BYTES>>>(0);
    k_epi2<<<dim3(NMT, C2 / BN), 128>>>(conv2_b);

    k_fc<512, 512><<<dim3(64, NWIN), 256>>>(l1_w, l1_b, pooled, m1);
    k_fc<512, 512><<<dim3(64, NWIN), 256>>>(l2_w, l2_b, m1, m2);
    k_fc<512, 128><<<dim3(16, NWIN), 256>>>(l3_w, l3_b, m2, out);
}

// round 10
// speedup vs baseline: 2.4363x; 1.0122x over previous
#include <cuda_runtime.h>
#include <cuda_bf16.h>
#include <mma.h>
#include <cstdint>

using namespace nvcuda;

constexpr int NWIN = 8, CH = 1024, C2 = 512;
constexpr int SLAB = 256, WINSLABS = 6, GUARD = 256;
constexpr int ROWS_ALLOC = NWIN * WINSLABS * SLAB + 2 * GUARD;  // 12800
constexpr int KDIM = 27 * CH;                                    // 27648
constexpr int BM = 128, BN = 128, BK = 32;

constexpr int VROWS = NWIN * 4 * 196;   // 6272 valid output rows
constexpr int NMT = VROWS / BM;         // 49 m-tiles (exact)
constexpr int SPLITS = 3;
constexpr int KCH = KDIM / BK / SPLITS; // 288 chunks per split (9 taps)

// bank-conflict-free smem strides (bytes ≡ 16 mod 32)
constexpr int LDA = 40;    // elements
constexpr int LDB = 136;   // elements
constexpr int LDSTG = 132; // fp32 staging stride

// 3-stage ring: per stage Ah,Al,Bh,Bl
constexpr int A_BUF = BM * LDA * 2;   // 10240 B
constexpr int B_BUF = BK * LDB * 2;   // 8704 B
constexpr int ST_AH = 0;
constexpr int ST_AL = A_BUF;              // 10240
constexpr int ST_BH = 2 * A_BUF;          // 20480
constexpr int ST_BL = 2 * A_BUF + B_BUF;  // 29184
constexpr int STAGE_B = 2 * A_BUF + 2 * B_BUF;  // 37888
constexpr int SMEM_BYTES = 3 * STAGE_B;         // 113664 (2 CTAs/SM)

__device__ __nv_bfloat16 g_X1h[(size_t)ROWS_ALLOC * CH];
__device__ __nv_bfloat16 g_X1l[(size_t)ROWS_ALLOC * CH];
__device__ __nv_bfloat16 g_X2h[(size_t)ROWS_ALLOC * CH];
__device__ __nv_bfloat16 g_X2l[(size_t)ROWS_ALLOC * CH];
__device__ __nv_bfloat16 g_W1Th[(size_t)KDIM * CH];   // [kidx*CH+ic][oc]
__device__ __nv_bfloat16 g_W1Tl[(size_t)KDIM * CH];
__device__ __nv_bfloat16 g_W2Th[(size_t)KDIM * C2];
__device__ __nv_bfloat16 g_W2Tl[(size_t)KDIM * C2];
__device__ float g_part[(size_t)SPLITS * NMT * 8 * BM * BN];  // fp32 partials
__device__ float g_pooled[NWIN * C2];
__device__ float g_m1[NWIN * 512];
__device__ float g_m2[NWIN * 512];

__device__ __forceinline__ void split_bf16(float v, __nv_bfloat16& hi, __nv_bfloat16& lo) {
    hi = __float2bfloat16(v);
    lo = __float2bfloat16(v - __bfloat162float(hi));
}

// valid-row index -> padded row in X layout
__device__ __forceinline__ int padded_row(int i) {
    int t = i / 784, rem = i - t * 784;
    int d = rem / 196, s = rem - d * 196;
    int h = s / 14, w = s - h * 14;
    return (t * WINSLABS + d + 1) * SLAB + (h + 1) * 16 + (w + 1);
}

__device__ __forceinline__ uint32_t smem_u32(const void* p) {
    uint32_t a;
    asm("{ .reg .u64 t; cvta.to.shared.u64 t, %1; cvt.u32.u64 %0, t; }" : "=r"(a) : "l"(p));
    return a;
}
#define CP_ASYNC16(dst, src) \
    asm volatile("cp.async.cg.shared.global [%0], [%1], 16;" :: "r"(dst), "l"(src))
#define CP_COMMIT() asm volatile("cp.async.commit_group;" ::: "memory")
#define CP_WAIT0()  asm volatile("cp.async.wait_group 0;" ::: "memory")
#define CP_WAIT1()  asm volatile("cp.async.wait_group 1;" ::: "memory")

// ---------------- prep kernels ----------------
__global__ void k_zero_pooled() {
    int i = blockIdx.x * 256 + threadIdx.x;
    if (i < NWIN * C2) g_pooled[i] = 0.f;
}

__global__ void k_gather(const float* __restrict__ videos) {
    int i = blockIdx.x * 256 + threadIdx.x;
    constexpr int TOT = NWIN * 4 * 14 * 14 * CH;
    if (i >= TOT) return;
    int c = i & (CH - 1);
    int rest = i >> 10;
    int w = rest % 14; rest /= 14;
    int h = rest % 14; rest /= 14;
    int d = rest & 3;
    int t = rest >> 2;
    int frame = t - 4 + d;  // window t holds frames t-4..t-1 (zeros before 0)
    float v = (frame >= 0) ? videos[(size_t)(frame * CH + c) * 196 + h * 14 + w] : 0.f;
    __nv_bfloat16 hi, lo; split_bf16(v, hi, lo);
    size_t dst = (size_t)(GUARD + (t * WINSLABS + d + 1) * SLAB + (h + 1) * 16 + (w + 1)) * CH + c;
    g_X1h[dst] = hi;
    g_X1l[dst] = lo;
}

template<int NOC>
__global__ void k_transpose(const float* __restrict__ w,
                            __nv_bfloat16* __restrict__ wth,
                            __nv_bfloat16* __restrict__ wtl) {
    __shared__ float s[32][28];
    int ocBase = blockIdx.x * 32;
    int ic = blockIdx.y;
    for (int idx = threadIdx.x; idx < 32 * 27; idx += 256) {
        int oc = idx / 27, kk = idx - oc * 27;
        s[oc][kk] = w[((size_t)(ocBase + oc) * CH + ic) * 27 + kk];
    }
    __syncthreads();
    for (int idx = threadIdx.x; idx < 27 * 32; idx += 256) {
        int kk = idx >> 5, oc = idx & 31;
        __nv_bfloat16 hi, lo; split_bf16(s[oc][kk], hi, lo);
        size_t o = ((size_t)kk * CH + ic) * NOC + ocBase + oc;
        wth[o] = hi;
        wtl[o] = lo;
    }
}

// ---- implicit-conv GEMM: compacted M, split-K, 3-stage cp.async, 1 sync/iter ----
template<int N, bool L2>
__global__ void __launch_bounds__(256, 2)
k_gemm(int dummy) {
    const __nv_bfloat16* __restrict__ Xh = (L2 ? g_X2h : g_X1h) + (size_t)GUARD * CH;
    const __nv_bfloat16* __restrict__ Xl = (L2 ? g_X2l : g_X1l) + (size_t)GUARD * CH;
    const __nv_bfloat16* __restrict__ Wh = L2 ? g_W2Th : g_W1Th;
    const __nv_bfloat16* __restrict__ Wl = L2 ? g_W2Tl : g_W1Tl;

    extern __shared__ __align__(128) char smem_raw[];
    const uint32_t sbase = smem_u32(smem_raw);

    const int tid = threadIdx.x;
    const int mtile = blockIdx.x;          // 0..48
    const int nBase = blockIdx.y * BN;
    const int split = blockIdx.z;          // 0..2
    const int k0 = split * KCH;

    // per-thread A source rows (fixed across K loop)
    const int r0 = tid >> 2;
    const long pr0 = padded_row(mtile * BM + r0);
    const long pr1 = padded_row(mtile * BM + r0 + 64);
    const int ac = (tid & 3) * 8;

    wmma::fragment<wmma::accumulator, 16, 16, 16, float> acc[4][2];
#pragma unroll
    for (int i = 0; i < 4; i++)
#pragma unroll
        for (int j = 0; j < 2; j++) wmma::fill_fragment(acc[i][j], 0.f);

    const int warpId = tid >> 5;
    const int warpM = warpId >> 2;
    const int warpN = warpId & 3;

    auto loadTile = [&](int kt, int stage) {
        const int kidx = kt >> 5;
        const int icBase = (kt & 31) << 5;
        const int kd = kidx / 9, r9 = kidx - kd * 9;
        const int kh = r9 / 3, kw = r9 - kh * 3;
        const long off = (long)(kd - 1) * SLAB + (kh - 1) * 16 + (kw - 1);
        const uint32_t sb = sbase + stage * STAGE_B;
#pragma unroll
        for (int it = 0; it < 2; it++) {
            const long so = ((it ? pr1 : pr0) + off) * CH + icBase + ac;
            const uint32_t do_ = (r0 + it * 64) * (LDA * 2) + (ac * 2);
            CP_ASYNC16(sb + ST_AH + do_, Xh + so);
            CP_ASYNC16(sb + ST_AL + do_, Xl + so);
        }
        const size_t wb = (size_t)kt * BK * N + nBase;
#pragma unroll
        for (int it = 0; it < 2; it++) {
            int v = it * 256 + tid;
            int row = v >> 4, c = v & 15;
            size_t so = wb + (size_t)row * N + c * 8;
            uint32_t do_ = row * (LDB * 2) + c * 16;
            CP_ASYNC16(sb + ST_BH + do_, Wh + so);
            CP_ASYNC16(sb + ST_BL + do_, Wl + so);
        }
    };

    loadTile(k0, 0);     CP_COMMIT();
    loadTile(k0 + 1, 1); CP_COMMIT();

    int stage = 0, nstage = 2;
    for (int kk = 0; kk < KCH; kk++) {
        if (kk < KCH - 1) CP_WAIT1(); else CP_WAIT0();
        __syncthreads();   // stage's data visible to all; prev readers of nstage done
        if (kk + 2 < KCH) {
            loadTile(k0 + kk + 2, nstage);
            CP_COMMIT();
        }
        const char* sb = smem_raw + stage * STAGE_B;
        const __nv_bfloat16* ah = (const __nv_bfloat16*)(sb + ST_AH);
        const __nv_bfloat16* al = (const __nv_bfloat16*)(sb + ST_AL);
        const __nv_bfloat16* bh = (const __nv_bfloat16*)(sb + ST_BH);
        const __nv_bfloat16* bl = (const __nv_bfloat16*)(sb + ST_BL);
#pragma unroll
        for (int ks = 0; ks < 2; ks++) {
            wmma::fragment<wmma::matrix_b, 16, 16, 16, __nv_bfloat16, wmma::row_major> fbh[2], fbl[2];
#pragma unroll
            for (int j = 0; j < 2; j++) {
                wmma::load_matrix_sync(fbh[j], bh + ks * 16 * LDB + warpN * 32 + j * 16, LDB);
                wmma::load_matrix_sync(fbl[j], bl + ks * 16 * LDB + warpN * 32 + j * 16, LDB);
            }
#pragma unroll
            for (int i = 0; i < 4; i++) {
                wmma::fragment<wmma::matrix_a, 16, 16, 16, __nv_bfloat16, wmma::row_major> fah, fal;
                wmma::load_matrix_sync(fah, ah + (warpM * 64 + i * 16) * LDA + ks * 16, LDA);
                wmma::load_matrix_sync(fal, al + (warpM * 64 + i * 16) * LDA + ks * 16, LDA);
#pragma unroll
                for (int j = 0; j < 2; j++) {
                    wmma::mma_sync(acc[i][j], fah, fbh[j], acc[i][j]);
                    wmma::mma_sync(acc[i][j], fah, fbl[j], acc[i][j]);
                    wmma::mma_sync(acc[i][j], fal, fbh[j], acc[i][j]);
                }
            }
        }
        stage = (stage + 1 == 3) ? 0 : stage + 1;
        nstage = (nstage + 1 == 3) ? 0 : nstage + 1;
    }
    __syncthreads();   // all mma reads done before smem reuse as staging

    // stage + coalesced fp32 partial store
    float* Stage = (float*)smem_raw;
#pragma unroll
    for (int i = 0; i < 4; i++)
#pragma unroll
        for (int j = 0; j < 2; j++)
            wmma::store_matrix_sync(Stage + (warpM * 64 + i * 16) * LDSTG + warpN * 32 + j * 16,
                                    acc[i][j], LDSTG, wmma::mem_row_major);
    __syncthreads();

    float* dst = g_part + ((size_t)(split * NMT + mtile) * 8 + blockIdx.y) * (BM * BN);
#pragma unroll
    for (int it = 0; it < 16; it++) {
        int v = it * 256 + tid;
        int row = v >> 5, c4 = (v & 31) * 4;
        *(float4*)(dst + row * BN + c4) = *(const float4*)(Stage + row * LDSTG + c4);
    }
}

// sum 3 partials + bias + relu -> X2 hi/lo at padded rows
__global__ void k_epi1(const float* __restrict__ bias) {
    const int mtile = blockIdx.x, nblk = blockIdx.y;
    const int col = threadIdx.x & 127, rh = threadIdx.x >> 7;
    const size_t tb = ((size_t)mtile * 8 + nblk) * (BM * BN);
    const float* P0 = g_part + tb;
    const float* P1 = g_part + (size_t)NMT * 8 * BM * BN + tb;
    const float* P2 = g_part + (size_t)2 * NMT * 8 * BM * BN + tb;
    const float b = bias[nblk * 128 + col];
    for (int rr = rh * 64; rr < rh * 64 + 64; rr++) {
        int e = rr * BN + col;
        float v = fmaxf(P0[e] + P1[e] + P2[e] + b, 0.f);
        __nv_bfloat16 hi, lo; split_bf16(v, hi, lo);
        size_t o = (size_t)(GUARD + padded_row(mtile * BM + rr)) * CH + nblk * 128 + col;
        g_X2h[o] = hi;
        g_X2l[o] = lo;
    }
}

// sum 3 partials + bias + relu + maxpool -> g_pooled
__global__ void k_epi2(const float* __restrict__ bias) {
    const int mtile = blockIdx.x, nblk = blockIdx.y;
    const int col = threadIdx.x;  // 128 threads
    const size_t tb = ((size_t)mtile * 8 + nblk) * (BM * BN);
    const float* P0 = g_part + tb;
    const float* P1 = g_part + (size_t)NMT * 8 * BM * BN + tb;
    const float* P2 = g_part + (size_t)2 * NMT * 8 * BM * BN + tb;
    const float b = bias[nblk * 128 + col];
    float m = 0.f;
    int curt = (mtile * BM) / 784;
    for (int rr = 0; rr < BM; rr++) {
        int t = (mtile * BM + rr) / 784;
        if (t != curt) {
            atomicMax((int*)&g_pooled[curt * C2 + nblk * 128 + col], __float_as_int(m));
            m = 0.f;
            curt = t;
        }
        int e = rr * BN + col;
        m = fmaxf(m, P0[e] + P1[e] + P2[e] + b);
    }
    atomicMax((int*)&g_pooled[curt * C2 + nblk * 128 + col], __float_as_int(m));
}

// ---------------- tiny MLP ----------------
template<int IN, int OUT>
__global__ void k_fc(const float* __restrict__ W, const float* __restrict__ b,
                     const float* __restrict__ x, float* __restrict__ y) {
    int w = threadIdx.x >> 5, lane = threadIdx.x & 31;
    int o = blockIdx.x * 8 + w, t = blockIdx.y;
    float s = 0.f;
    for (int i = lane; i < IN; i += 32) s += x[t * IN + i] * W[(size_t)o * IN + i];
#pragma unroll
    for (int d = 16; d; d >>= 1) s += __shfl_down_sync(0xffffffffu, s, d);
    if (lane == 0) y[t * OUT + o] = fmaxf(s + b[o], 0.f);
}

extern "C" void kernel_launch(void* const* d_in, const int* in_sizes, int n_in,
                              void* d_out, int out_size) {
    const float* videos  = (const float*)d_in[0];
    const float* conv1_w = (const float*)d_in[1];
    const float* conv1_b = (const float*)d_in[2];
    const float* conv2_w = (const float*)d_in[3];
    const float* conv2_b = (const float*)d_in[4];
    const float* l1_w = (const float*)d_in[5];
    const float* l1_b = (const float*)d_in[6];
    const float* l2_w = (const float*)d_in[7];
    const float* l2_b = (const float*)d_in[8];
    const float* l3_w = (const float*)d_in[9];
    const float* l3_b = (const float*)d_in[10];
    float* out = (float*)d_out;

    cudaFuncSetAttribute(k_gemm<CH, false>, cudaFuncAttributeMaxDynamicSharedMemorySize, SMEM_BYTES);
    cudaFuncSetAttribute(k_gemm<C2, true>,  cudaFuncAttributeMaxDynamicSharedMemorySize, SMEM_BYTES);

    __nv_bfloat16 *w1th, *w1tl, *w2th, *w2tl;
    float *pooled, *m1, *m2;
    cudaGetSymbolAddress((void**)&w1th, g_W1Th);
    cudaGetSymbolAddress((void**)&w1tl, g_W1Tl);
    cudaGetSymbolAddress((void**)&w2th, g_W2Th);
    cudaGetSymbolAddress((void**)&w2tl, g_W2Tl);
    cudaGetSymbolAddress((void**)&pooled, g_pooled);
    cudaGetSymbolAddress((void**)&m1, g_m1);
    cudaGetSymbolAddress((void**)&m2, g_m2);

    constexpr int TOT = NWIN * 4 * 14 * 14 * CH;
    k_gather<<<(TOT + 255) / 256, 256>>>(videos);
    k_transpose<CH><<<dim3(CH / 32, CH), 256>>>(conv1_w, w1th, w1tl);
    k_transpose<C2><<<dim3(C2 / 32, CH), 256>>>(conv2_w, w2th, w2tl);
    k_zero_pooled<<<(NWIN * C2 + 255) / 256, 256>>>();
    k_zero_pooled<<<(NWIN * C2 + 255) / 256, 256>>>();  // idempotent; aligns ncu -s 5 onto the GEMM

    k_gemm<CH, false><<<dim3(NMT, CH / BN, SPLITS), 256, SMEM_BYTES>>>(0);
    k_epi1<<<dim3(NMT, CH / BN), 256>>>(conv1_b);

    k_gemm<C2, true><<<dim3(NMT, C2 / BN, SPLITS), 256, SMEM_BYTES>>>(0);
    k_epi2<<<dim3(NMT, C2 / BN), 128>>>(conv2_b);

    k_fc<512, 512><<<dim3(64, NWIN), 256>>>(l1_w, l1_b, pooled, m1);
    k_fc<512, 512><<<dim3(64, NWIN), 256>>>(l2_w, l2_b, m1, m2);
    k_fc<512, 128><<<dim3(16, NWIN), 256>>>(l3_w, l3_b, m2, out);
}

// round 11
// speedup vs baseline: 2.7251x; 1.1186x over previous
#include <cuda_runtime.h>
#include <cuda_bf16.h>
#include <mma.h>
#include <cstdint>

using namespace nvcuda;

constexpr int NWIN = 8, CH = 1024, C2 = 512;
constexpr int SLAB = 256, WINSLABS = 6, GUARD = 256;
constexpr int ROWS_ALLOC = NWIN * WINSLABS * SLAB + 2 * GUARD;  // 12800
constexpr int KDIM = 27 * CH;                                    // 27648
constexpr int BM = 128, BN = 128, BK = 32;
constexpr int KCHUNKS = KDIM / BK;                               // 864

// conv1: 7 zero-partial slabs skipped -> 25 slabs * 196 = 4900 valid rows
constexpr int VROWS1 = 4900;
constexpr int NMT1 = 39;            // ceil(4900/128), last tile has 92 dummy rows
constexpr int SPLITS1 = 8;          // 108 chunks per unit
constexpr int KCH1 = KCHUNKS / SPLITS1;
// conv2: all 6272 rows
constexpr int VROWS2 = 6272;
constexpr int NMT2 = 49;
constexpr int SPLITS2 = 3;          // 288 chunks per unit
constexpr int KCH2 = KCHUNKS / SPLITS2;

// bank-conflict-free smem strides (bytes ≡ 16 mod 32)
constexpr int LDA = 40;    // elements
constexpr int LDB = 136;   // elements
constexpr int LDSTG = 132; // fp32 staging stride

// 3-stage ring: per stage Ah,Al,Bh,Bl
constexpr int A_BUF = BM * LDA * 2;   // 10240 B
constexpr int B_BUF = BK * LDB * 2;   // 8704 B
constexpr int ST_AH = 0;
constexpr int ST_AL = A_BUF;
constexpr int ST_BH = 2 * A_BUF;
constexpr int ST_BL = 2 * A_BUF + B_BUF;
constexpr int STAGE_B = 2 * A_BUF + 2 * B_BUF;  // 37888
constexpr int SMEM_BYTES = 3 * STAGE_B;         // 113664 (2 CTAs/SM)

__device__ __nv_bfloat16 g_X1h[(size_t)ROWS_ALLOC * CH];
__device__ __nv_bfloat16 g_X1l[(size_t)ROWS_ALLOC * CH];
__device__ __nv_bfloat16 g_X2h[(size_t)ROWS_ALLOC * CH];
__device__ __nv_bfloat16 g_X2l[(size_t)ROWS_ALLOC * CH];
__device__ __nv_bfloat16 g_W1Th[(size_t)KDIM * CH];   // [kidx*CH+ic][oc]
__device__ __nv_bfloat16 g_W1Tl[(size_t)KDIM * CH];
__device__ __nv_bfloat16 g_W2Th[(size_t)KDIM * C2];
__device__ __nv_bfloat16 g_W2Tl[(size_t)KDIM * C2];
// partials: conv1 needs SPLITS1*NMT1*8 = 2496 tiles; conv2 reuses (588 tiles)
__device__ float g_part[(size_t)SPLITS1 * NMT1 * 8 * BM * BN];
__device__ float g_pooled[NWIN * C2];
__device__ float g_m1[NWIN * 512];
__device__ float g_m2[NWIN * 512];

__device__ __forceinline__ void split_bf16(float v, __nv_bfloat16& hi, __nv_bfloat16& lo) {
    hi = __float2bfloat16(v);
    lo = __float2bfloat16(v - __bfloat162float(hi));
}

// conv2 valid-row index (all 32 slabs) -> padded row
__device__ __forceinline__ int padded_row2(int i) {
    int t = i / 784, rem = i - t * 784;
    int d = rem / 196, s = rem - d * 196;
    int h = s / 14, w = s - h * 14;
    return (t * WINSLABS + d + 1) * SLAB + (h + 1) * 16 + (w + 1);
}

// conv1 compacted-row index (25 nonzero slabs) -> padded row; dummy rows -> 273 (safe)
__device__ __forceinline__ int padded_row1(int i) {
    if (i >= VROWS1) return 273;          // min legal padded row; ±273 taps stay in-bounds
    int s = i / 196, pos = i - s * 196;
    int t, d;
    if (s < 2)      { t = 1; d = s + 2; }
    else if (s < 5) { t = 2; d = s - 1; }
    else            { int q = s - 5; t = 3 + (q >> 2); d = q & 3; }
    int h = pos / 14, w = pos - h * 14;
    return (t * WINSLABS + d + 1) * SLAB + (h + 1) * 16 + (w + 1);
}

__device__ __forceinline__ uint32_t smem_u32(const void* p) {
    uint32_t a;
    asm("{ .reg .u64 t; cvta.to.shared.u64 t, %1; cvt.u32.u64 %0, t; }" : "=r"(a) : "l"(p));
    return a;
}
#define CP_ASYNC16(dst, src) \
    asm volatile("cp.async.cg.shared.global [%0], [%1], 16;" :: "r"(dst), "l"(src))
#define CP_COMMIT() asm volatile("cp.async.commit_group;" ::: "memory")
#define CP_WAIT0()  asm volatile("cp.async.wait_group 0;" ::: "memory")
#define CP_WAIT1()  asm volatile("cp.async.wait_group 1;" ::: "memory")

// ---------------- prep kernels ----------------
__global__ void k_zero_pooled() {
    int i = blockIdx.x * 256 + threadIdx.x;
    if (i < NWIN * C2) g_pooled[i] = 0.f;
}

__global__ void k_gather(const float* __restrict__ videos) {
    int i = blockIdx.x * 256 + threadIdx.x;
    constexpr int TOT = NWIN * 4 * 14 * 14 * CH;
    if (i >= TOT) return;
    int c = i & (CH - 1);
    int rest = i >> 10;
    int w = rest % 14; rest /= 14;
    int h = rest % 14; rest /= 14;
    int d = rest & 3;
    int t = rest >> 2;
    int frame = t - 4 + d;  // window t holds frames t-4..t-1 (zeros before 0)
    float v = (frame >= 0) ? videos[(size_t)(frame * CH + c) * 196 + h * 14 + w] : 0.f;
    __nv_bfloat16 hi, lo; split_bf16(v, hi, lo);
    size_t dst = (size_t)(GUARD + (t * WINSLABS + d + 1) * SLAB + (h + 1) * 16 + (w + 1)) * CH + c;
    g_X1h[dst] = hi;
    g_X1l[dst] = lo;
}

// fill the 7 all-zero-input conv1 output slabs with relu(b1) (conv of zeros = 0)
__global__ void k_fill(const float* __restrict__ b1) {
    int i = blockIdx.x * 256 + threadIdx.x;
    constexpr int TOT = 7 * 196 * CH;
    if (i >= TOT) return;
    int c = i & (CH - 1);
    int rest = i >> 10;              // slab*196 + pos
    int s2 = rest / 196, pos = rest - s2 * 196;
    int t = (s2 < 4) ? 0 : (s2 < 6) ? 1 : 2;
    int d = (s2 < 4) ? s2 : (s2 < 6) ? s2 - 4 : 0;
    int h = pos / 14, w = pos - h * 14;
    float v = fmaxf(b1[c], 0.f);
    __nv_bfloat16 hi, lo; split_bf16(v, hi, lo);
    size_t o = (size_t)(GUARD + (t * WINSLABS + d + 1) * SLAB + (h + 1) * 16 + (w + 1)) * CH + c;
    g_X2h[o] = hi;
    g_X2l[o] = lo;
}

template<int NOC>
__global__ void k_transpose(const float* __restrict__ w,
                            __nv_bfloat16* __restrict__ wth,
                            __nv_bfloat16* __restrict__ wtl) {
    __shared__ float s[32][28];
    int ocBase = blockIdx.x * 32;
    int ic = blockIdx.y;
    for (int idx = threadIdx.x; idx < 32 * 27; idx += 256) {
        int oc = idx / 27, kk = idx - oc * 27;
        s[oc][kk] = w[((size_t)(ocBase + oc) * CH + ic) * 27 + kk];
    }
    __syncthreads();
    for (int idx = threadIdx.x; idx < 27 * 32; idx += 256) {
        int kk = idx >> 5, oc = idx & 31;
        __nv_bfloat16 hi, lo; split_bf16(s[oc][kk], hi, lo);
        size_t o = ((size_t)kk * CH + ic) * NOC + ocBase + oc;
        wth[o] = hi;
        wtl[o] = lo;
    }
}

// ---- implicit-conv GEMM: compacted M, split-K, 3-stage cp.async ----
template<int N, bool L2, int SPL, int NMT, int KCH>
__global__ void __launch_bounds__(256, 2)
k_gemm(int dummy) {
    const __nv_bfloat16* __restrict__ Xh = (L2 ? g_X2h : g_X1h) + (size_t)GUARD * CH;
    const __nv_bfloat16* __restrict__ Xl = (L2 ? g_X2l : g_X1l) + (size_t)GUARD * CH;
    const __nv_bfloat16* __restrict__ Wh = L2 ? g_W2Th : g_W1Th;
    const __nv_bfloat16* __restrict__ Wl = L2 ? g_W2Tl : g_W1Tl;
    constexpr int NB = N / BN;

    extern __shared__ __align__(128) char smem_raw[];
    const uint32_t sbase = smem_u32(smem_raw);

    const int tid = threadIdx.x;
    const int mtile = blockIdx.x;
    const int nBase = blockIdx.y * BN;
    const int split = blockIdx.z;
    const int k0 = split * KCH;

    const int r0 = tid >> 2;
    const long pr0 = L2 ? padded_row2(mtile * BM + r0)      : padded_row1(mtile * BM + r0);
    const long pr1 = L2 ? padded_row2(mtile * BM + r0 + 64) : padded_row1(mtile * BM + r0 + 64);
    const int ac = (tid & 3) * 8;

    wmma::fragment<wmma::accumulator, 16, 16, 16, float> acc[4][2];
#pragma unroll
    for (int i = 0; i < 4; i++)
#pragma unroll
        for (int j = 0; j < 2; j++) wmma::fill_fragment(acc[i][j], 0.f);

    const int warpId = tid >> 5;
    const int warpM = warpId >> 2;
    const int warpN = warpId & 3;

    auto loadTile = [&](int kt, int stage) {
        const int kidx = kt >> 5;
        const int icBase = (kt & 31) << 5;
        const int kd = kidx / 9, r9 = kidx - kd * 9;
        const int kh = r9 / 3, kw = r9 - kh * 3;
        const long off = (long)(kd - 1) * SLAB + (kh - 1) * 16 + (kw - 1);
        const uint32_t sb = sbase + stage * STAGE_B;
#pragma unroll
        for (int it = 0; it < 2; it++) {
            const long so = ((it ? pr1 : pr0) + off) * CH + icBase + ac;
            const uint32_t do_ = (r0 + it * 64) * (LDA * 2) + (ac * 2);
            CP_ASYNC16(sb + ST_AH + do_, Xh + so);
            CP_ASYNC16(sb + ST_AL + do_, Xl + so);
        }
        const size_t wb = (size_t)kt * BK * N + nBase;
#pragma unroll
        for (int it = 0; it < 2; it++) {
            int v = it * 256 + tid;
            int row = v >> 4, c = v & 15;
            size_t so = wb + (size_t)row * N + c * 8;
            uint32_t do_ = row * (LDB * 2) + c * 16;
            CP_ASYNC16(sb + ST_BH + do_, Wh + so);
            CP_ASYNC16(sb + ST_BL + do_, Wl + so);
        }
    };

    loadTile(k0, 0);     CP_COMMIT();
    loadTile(k0 + 1, 1); CP_COMMIT();

    int stage = 0, nstage = 2;
    for (int kk = 0; kk < KCH; kk++) {
        if (kk < KCH - 1) CP_WAIT1(); else CP_WAIT0();
        __syncthreads();
        if (kk + 2 < KCH) {
            loadTile(k0 + kk + 2, nstage);
            CP_COMMIT();
        }
        const char* sb = smem_raw + stage * STAGE_B;
        const __nv_bfloat16* ah = (const __nv_bfloat16*)(sb + ST_AH);
        const __nv_bfloat16* al = (const __nv_bfloat16*)(sb + ST_AL);
        const __nv_bfloat16* bh = (const __nv_bfloat16*)(sb + ST_BH);
        const __nv_bfloat16* bl = (const __nv_bfloat16*)(sb + ST_BL);
#pragma unroll
        for (int ks = 0; ks < 2; ks++) {
            wmma::fragment<wmma::matrix_b, 16, 16, 16, __nv_bfloat16, wmma::row_major> fbh[2], fbl[2];
#pragma unroll
            for (int j = 0; j < 2; j++) {
                wmma::load_matrix_sync(fbh[j], bh + ks * 16 * LDB + warpN * 32 + j * 16, LDB);
                wmma::load_matrix_sync(fbl[j], bl + ks * 16 * LDB + warpN * 32 + j * 16, LDB);
            }
#pragma unroll
            for (int i = 0; i < 4; i++) {
                wmma::fragment<wmma::matrix_a, 16, 16, 16, __nv_bfloat16, wmma::row_major> fah, fal;
                wmma::load_matrix_sync(fah, ah + (warpM * 64 + i * 16) * LDA + ks * 16, LDA);
                wmma::load_matrix_sync(fal, al + (warpM * 64 + i * 16) * LDA + ks * 16, LDA);
#pragma unroll
                for (int j = 0; j < 2; j++) {
                    wmma::mma_sync(acc[i][j], fah, fbh[j], acc[i][j]);
                    wmma::mma_sync(acc[i][j], fah, fbl[j], acc[i][j]);
                    wmma::mma_sync(acc[i][j], fal, fbh[j], acc[i][j]);
                }
            }
        }
        stage = (stage + 1 == 3) ? 0 : stage + 1;
        nstage = (nstage + 1 == 3) ? 0 : nstage + 1;
    }
    __syncthreads();

    float* Stage = (float*)smem_raw;
#pragma unroll
    for (int i = 0; i < 4; i++)
#pragma unroll
        for (int j = 0; j < 2; j++)
            wmma::store_matrix_sync(Stage + (warpM * 64 + i * 16) * LDSTG + warpN * 32 + j * 16,
                                    acc[i][j], LDSTG, wmma::mem_row_major);
    __syncthreads();

    float* dst = g_part + ((size_t)(split * NMT + mtile) * NB + blockIdx.y) * (BM * BN);
#pragma unroll
    for (int it = 0; it < 16; it++) {
        int v = it * 256 + tid;
        int row = v >> 5, c4 = (v & 31) * 4;
        *(float4*)(dst + row * BN + c4) = *(const float4*)(Stage + row * LDSTG + c4);
    }
}

// conv1 epilogue: sum SPLITS1 partials + bias + relu -> X2 hi/lo (skip dummy rows)
__global__ void k_epi1(const float* __restrict__ bias) {
    const int mtile = blockIdx.x, nblk = blockIdx.y;
    const int col = threadIdx.x & 127, rh = threadIdx.x >> 7;
    const size_t tile_sz = (size_t)BM * BN;
    const size_t tb = ((size_t)mtile * 8 + nblk) * tile_sz;
    const float b = bias[nblk * 128 + col];
    for (int rr = rh * 64; rr < rh * 64 + 64; rr++) {
        int gi = mtile * BM + rr;
        if (gi >= VROWS1) break;
        int e = rr * BN + col;
        float v = 0.f;
#pragma unroll
        for (int s = 0; s < SPLITS1; s++)
            v += g_part[(size_t)s * NMT1 * 8 * tile_sz + tb + e];
        v = fmaxf(v + b, 0.f);
        __nv_bfloat16 hi, lo; split_bf16(v, hi, lo);
        size_t o = (size_t)(GUARD + padded_row1(gi)) * CH + nblk * 128 + col;
        g_X2h[o] = hi;
        g_X2l[o] = lo;
    }
}

// conv2 epilogue: sum SPLITS2 partials + bias + relu + maxpool -> g_pooled
__global__ void k_epi2(const float* __restrict__ bias) {
    const int mtile = blockIdx.x, nblk = blockIdx.y;
    const int col = threadIdx.x;  // 128 threads
    const size_t tile_sz = (size_t)BM * BN;
    const size_t tb = ((size_t)mtile * 4 + nblk) * tile_sz;
    const float* P0 = g_part + tb;
    const float* P1 = g_part + (size_t)NMT2 * 4 * tile_sz + tb;
    const float* P2 = g_part + (size_t)2 * NMT2 * 4 * tile_sz + tb;
    const float b = bias[nblk * 128 + col];
    float m = 0.f;
    int curt = (mtile * BM) / 784;
    for (int rr = 0; rr < BM; rr++) {
        int t = (mtile * BM + rr) / 784;
        if (t != curt) {
            atomicMax((int*)&g_pooled[curt * C2 + nblk * 128 + col], __float_as_int(m));
            m = 0.f;
            curt = t;
        }
        int e = rr * BN + col;
        m = fmaxf(m, P0[e] + P1[e] + P2[e] + b);
    }
    atomicMax((int*)&g_pooled[curt * C2 + nblk * 128 + col], __float_as_int(m));
}

// ---------------- tiny MLP ----------------
template<int IN, int OUT>
__global__ void k_fc(const float* __restrict__ W, const float* __restrict__ b,
                     const float* __restrict__ x, float* __restrict__ y) {
    int w = threadIdx.x >> 5, lane = threadIdx.x & 31;
    int o = blockIdx.x * 8 + w, t = blockIdx.y;
    float s = 0.f;
    for (int i = lane; i < IN; i += 32) s += x[t * IN + i] * W[(size_t)o * IN + i];
#pragma unroll
    for (int d = 16; d; d >>= 1) s += __shfl_down_sync(0xffffffffu, s, d);
    if (lane == 0) y[t * OUT + o] = fmaxf(s + b[o], 0.f);
}

extern "C" void kernel_launch(void* const* d_in, const int* in_sizes, int n_in,
                              void* d_out, int out_size) {
    const float* videos  = (const float*)d_in[0];
    const float* conv1_w = (const float*)d_in[1];
    const float* conv1_b = (const float*)d_in[2];
    const float* conv2_w = (const float*)d_in[3];
    const float* conv2_b = (const float*)d_in[4];
    const float* l1_w = (const float*)d_in[5];
    const float* l1_b = (const float*)d_in[6];
    const float* l2_w = (const float*)d_in[7];
    const float* l2_b = (const float*)d_in[8];
    const float* l3_w = (const float*)d_in[9];
    const float* l3_b = (const float*)d_in[10];
    float* out = (float*)d_out;

    auto g1 = k_gemm<CH, false, SPLITS1, NMT1, KCH1>;
    auto g2 = k_gemm<C2, true,  SPLITS2, NMT2, KCH2>;
    cudaFuncSetAttribute(g1, cudaFuncAttributeMaxDynamicSharedMemorySize, SMEM_BYTES);
    cudaFuncSetAttribute(g2, cudaFuncAttributeMaxDynamicSharedMemorySize, SMEM_BYTES);

    __nv_bfloat16 *w1th, *w1tl, *w2th, *w2tl;
    float *pooled, *m1, *m2;
    cudaGetSymbolAddress((void**)&w1th, g_W1Th);
    cudaGetSymbolAddress((void**)&w1tl, g_W1Tl);
    cudaGetSymbolAddress((void**)&w2th, g_W2Th);
    cudaGetSymbolAddress((void**)&w2tl, g_W2Tl);
    cudaGetSymbolAddress((void**)&pooled, g_pooled);
    cudaGetSymbolAddress((void**)&m1, g_m1);
    cudaGetSymbolAddress((void**)&m2, g_m2);

    constexpr int TOT = NWIN * 4 * 14 * 14 * CH;
    k_gather<<<(TOT + 255) / 256, 256>>>(videos);
    k_transpose<CH><<<dim3(CH / 32, CH), 256>>>(conv1_w, w1th, w1tl);
    k_transpose<C2><<<dim3(C2 / 32, CH), 256>>>(conv2_w, w2th, w2tl);
    k_zero_pooled<<<(NWIN * C2 + 255) / 256, 256>>>();
    k_fill<<<(7 * 196 * CH + 255) / 256, 256>>>(conv1_b);

    g1<<<dim3(NMT1, CH / BN, SPLITS1), 256, SMEM_BYTES>>>(0);
    k_epi1<<<dim3(NMT1, CH / BN), 256>>>(conv1_b);

    g2<<<dim3(NMT2, C2 / BN, SPLITS2), 256, SMEM_BYTES>>>(0);
    k_epi2<<<dim3(NMT2, C2 / BN), 128>>>(conv2_b);

    k_fc<512, 512><<<dim3(64, NWIN), 256>>>(l1_w, l1_b, pooled, m1);
    k_fc<512, 512><<<dim3(64, NWIN), 256>>>(l2_w, l2_b, m1, m2);
    k_fc<512, 128><<<dim3(16, NWIN), 256>>>(l3_w, l3_b, m2, out);
}

// round 12
// speedup vs baseline: 2.7374x; 1.0045x over previous
#include <cuda_runtime.h>
#include <cuda_bf16.h>
#include <mma.h>
#include <cstdint>

using namespace nvcuda;

constexpr int NWIN = 8, CH = 1024, C2 = 512;
constexpr int SLAB = 256, WINSLABS = 6, GUARD = 256;
constexpr int ROWS_ALLOC = NWIN * WINSLABS * SLAB + 2 * GUARD;  // 12800
constexpr int KDIM = 27 * CH;                                    // 27648
constexpr int BM = 128, BN = 128, BK = 32;
constexpr int KCHUNKS = KDIM / BK;                               // 864

// conv1: 7 zero-partial slabs skipped -> 25 slabs * 196 = 4900 valid rows
constexpr int VROWS1 = 4900;
constexpr int NMT1 = 39;            // ceil(4900/128), last tile has 92 dummy rows
constexpr int SPLITS1 = 16;         // 54 chunks per unit: 17 waves x 54 beats 9 x 108
constexpr int KCH1 = KCHUNKS / SPLITS1;   // 54
// conv2: all 6272 rows
constexpr int VROWS2 = 6272;
constexpr int NMT2 = 49;
constexpr int SPLITS2 = 3;          // 288 chunks per unit (2 waves, 98.6% packed)
constexpr int KCH2 = KCHUNKS / SPLITS2;

// bank-conflict-free smem strides (bytes ≡ 16 mod 32)
constexpr int LDA = 40;    // elements
constexpr int LDB = 136;   // elements
constexpr int LDSTG = 132; // fp32 staging stride

// 3-stage ring: per stage Ah,Al,Bh,Bl
constexpr int A_BUF = BM * LDA * 2;   // 10240 B
constexpr int B_BUF = BK * LDB * 2;   // 8704 B
constexpr int ST_AH = 0;
constexpr int ST_AL = A_BUF;
constexpr int ST_BH = 2 * A_BUF;
constexpr int ST_BL = 2 * A_BUF + B_BUF;
constexpr int STAGE_B = 2 * A_BUF + 2 * B_BUF;  // 37888
constexpr int SMEM_BYTES = 3 * STAGE_B;         // 113664 (2 CTAs/SM)

__device__ __nv_bfloat16 g_X1h[(size_t)ROWS_ALLOC * CH];
__device__ __nv_bfloat16 g_X1l[(size_t)ROWS_ALLOC * CH];
__device__ __nv_bfloat16 g_X2h[(size_t)ROWS_ALLOC * CH];
__device__ __nv_bfloat16 g_X2l[(size_t)ROWS_ALLOC * CH];
__device__ __nv_bfloat16 g_W1Th[(size_t)KDIM * CH];   // [kidx*CH+ic][oc]
__device__ __nv_bfloat16 g_W1Tl[(size_t)KDIM * CH];
__device__ __nv_bfloat16 g_W2Th[(size_t)KDIM * C2];
__device__ __nv_bfloat16 g_W2Tl[(size_t)KDIM * C2];
// partials: conv1 needs SPLITS1*NMT1*8 = 4992 tiles (327 MB); conv2 reuses (588 tiles)
__device__ float g_part[(size_t)SPLITS1 * NMT1 * 8 * BM * BN];
__device__ float g_pooled[NWIN * C2];
__device__ float g_m1[NWIN * 512];
__device__ float g_m2[NWIN * 512];

__device__ __forceinline__ void split_bf16(float v, __nv_bfloat16& hi, __nv_bfloat16& lo) {
    hi = __float2bfloat16(v);
    lo = __float2bfloat16(v - __bfloat162float(hi));
}

// conv2 valid-row index (all 32 slabs) -> padded row
__device__ __forceinline__ int padded_row2(int i) {
    int t = i / 784, rem = i - t * 784;
    int d = rem / 196, s = rem - d * 196;
    int h = s / 14, w = s - h * 14;
    return (t * WINSLABS + d + 1) * SLAB + (h + 1) * 16 + (w + 1);
}

// conv1 compacted-row index (25 nonzero slabs) -> padded row; dummy rows -> 273 (safe)
__device__ __forceinline__ int padded_row1(int i) {
    if (i >= VROWS1) return 273;          // min legal padded row; ±273 taps stay in-bounds
    int s = i / 196, pos = i - s * 196;
    int t, d;
    if (s < 2)      { t = 1; d = s + 2; }
    else if (s < 5) { t = 2; d = s - 1; }
    else            { int q = s - 5; t = 3 + (q >> 2); d = q & 3; }
    int h = pos / 14, w = pos - h * 14;
    return (t * WINSLABS + d + 1) * SLAB + (h + 1) * 16 + (w + 1);
}

__device__ __forceinline__ uint32_t smem_u32(const void* p) {
    uint32_t a;
    asm("{ .reg .u64 t; cvta.to.shared.u64 t, %1; cvt.u32.u64 %0, t; }" : "=r"(a) : "l"(p));
    return a;
}
#define CP_ASYNC16(dst, src) \
    asm volatile("cp.async.cg.shared.global [%0], [%1], 16;" :: "r"(dst), "l"(src))
#define CP_COMMIT() asm volatile("cp.async.commit_group;" ::: "memory")
#define CP_WAIT0()  asm volatile("cp.async.wait_group 0;" ::: "memory")
#define CP_WAIT1()  asm volatile("cp.async.wait_group 1;" ::: "memory")

// ---------------- prep kernels ----------------
__global__ void k_zero_pooled() {
    int i = blockIdx.x * 256 + threadIdx.x;
    if (i < NWIN * C2) g_pooled[i] = 0.f;
}

__global__ void k_gather(const float* __restrict__ videos) {
    int i = blockIdx.x * 256 + threadIdx.x;
    constexpr int TOT = NWIN * 4 * 14 * 14 * CH;
    if (i >= TOT) return;
    int c = i & (CH - 1);
    int rest = i >> 10;
    int w = rest % 14; rest /= 14;
    int h = rest % 14; rest /= 14;
    int d = rest & 3;
    int t = rest >> 2;
    int frame = t - 4 + d;  // window t holds frames t-4..t-1 (zeros before 0)
    float v = (frame >= 0) ? videos[(size_t)(frame * CH + c) * 196 + h * 14 + w] : 0.f;
    __nv_bfloat16 hi, lo; split_bf16(v, hi, lo);
    size_t dst = (size_t)(GUARD + (t * WINSLABS + d + 1) * SLAB + (h + 1) * 16 + (w + 1)) * CH + c;
    g_X1h[dst] = hi;
    g_X1l[dst] = lo;
}

// fill the 7 all-zero-input conv1 output slabs with relu(b1)
__global__ void k_fill(const float* __restrict__ b1) {
    int i = blockIdx.x * 256 + threadIdx.x;
    constexpr int TOT = 7 * 196 * CH;
    if (i >= TOT) return;
    int c = i & (CH - 1);
    int rest = i >> 10;
    int s2 = rest / 196, pos = rest - s2 * 196;
    int t = (s2 < 4) ? 0 : (s2 < 6) ? 1 : 2;
    int d = (s2 < 4) ? s2 : (s2 < 6) ? s2 - 4 : 0;
    int h = pos / 14, w = pos - h * 14;
    float v = fmaxf(b1[c], 0.f);
    __nv_bfloat16 hi, lo; split_bf16(v, hi, lo);
    size_t o = (size_t)(GUARD + (t * WINSLABS + d + 1) * SLAB + (h + 1) * 16 + (w + 1)) * CH + c;
    g_X2h[o] = hi;
    g_X2l[o] = lo;
}

template<int NOC>
__global__ void k_transpose(const float* __restrict__ w,
                            __nv_bfloat16* __restrict__ wth,
                            __nv_bfloat16* __restrict__ wtl) {
    __shared__ float s[32][28];
    int ocBase = blockIdx.x * 32;
    int ic = blockIdx.y;
    for (int idx = threadIdx.x; idx < 32 * 27; idx += 256) {
        int oc = idx / 27, kk = idx - oc * 27;
        s[oc][kk] = w[((size_t)(ocBase + oc) * CH + ic) * 27 + kk];
    }
    __syncthreads();
    for (int idx = threadIdx.x; idx < 27 * 32; idx += 256) {
        int kk = idx >> 5, oc = idx & 31;
        __nv_bfloat16 hi, lo; split_bf16(s[oc][kk], hi, lo);
        size_t o = ((size_t)kk * CH + ic) * NOC + ocBase + oc;
        wth[o] = hi;
        wtl[o] = lo;
    }
}

// ---- implicit-conv GEMM: compacted M, split-K, 3-stage cp.async ----
template<int N, bool L2, int SPL, int NMT, int KCH>
__global__ void __launch_bounds__(256, 2)
k_gemm(int dummy) {
    const __nv_bfloat16* __restrict__ Xh = (L2 ? g_X2h : g_X1h) + (size_t)GUARD * CH;
    const __nv_bfloat16* __restrict__ Xl = (L2 ? g_X2l : g_X1l) + (size_t)GUARD * CH;
    const __nv_bfloat16* __restrict__ Wh = L2 ? g_W2Th : g_W1Th;
    const __nv_bfloat16* __restrict__ Wl = L2 ? g_W2Tl : g_W1Tl;
    constexpr int NB = N / BN;

    extern __shared__ __align__(128) char smem_raw[];
    const uint32_t sbase = smem_u32(smem_raw);

    const int tid = threadIdx.x;
    const int mtile = blockIdx.x;
    const int nBase = blockIdx.y * BN;
    const int split = blockIdx.z;
    const int k0 = split * KCH;

    const int r0 = tid >> 2;
    const long pr0 = L2 ? padded_row2(mtile * BM + r0)      : padded_row1(mtile * BM + r0);
    const long pr1 = L2 ? padded_row2(mtile * BM + r0 + 64) : padded_row1(mtile * BM + r0 + 64);
    const int ac = (tid & 3) * 8;

    wmma::fragment<wmma::accumulator, 16, 16, 16, float> acc[4][2];
#pragma unroll
    for (int i = 0; i < 4; i++)
#pragma unroll
        for (int j = 0; j < 2; j++) wmma::fill_fragment(acc[i][j], 0.f);

    const int warpId = tid >> 5;
    const int warpM = warpId >> 2;
    const int warpN = warpId & 3;

    auto loadTile = [&](int kt, int stage) {
        const int kidx = kt >> 5;
        const int icBase = (kt & 31) << 5;
        const int kd = kidx / 9, r9 = kidx - kd * 9;
        const int kh = r9 / 3, kw = r9 - kh * 3;
        const long off = (long)(kd - 1) * SLAB + (kh - 1) * 16 + (kw - 1);
        const uint32_t sb = sbase + stage * STAGE_B;
#pragma unroll
        for (int it = 0; it < 2; it++) {
            const long so = ((it ? pr1 : pr0) + off) * CH + icBase + ac;
            const uint32_t do_ = (r0 + it * 64) * (LDA * 2) + (ac * 2);
            CP_ASYNC16(sb + ST_AH + do_, Xh + so);
            CP_ASYNC16(sb + ST_AL + do_, Xl + so);
        }
        const size_t wb = (size_t)kt * BK * N + nBase;
#pragma unroll
        for (int it = 0; it < 2; it++) {
            int v = it * 256 + tid;
            int row = v >> 4, c = v & 15;
            size_t so = wb + (size_t)row * N + c * 8;
            uint32_t do_ = row * (LDB * 2) + c * 16;
            CP_ASYNC16(sb + ST_BH + do_, Wh + so);
            CP_ASYNC16(sb + ST_BL + do_, Wl + so);
        }
    };

    loadTile(k0, 0);     CP_COMMIT();
    loadTile(k0 + 1, 1); CP_COMMIT();

    int stage = 0, nstage = 2;
    for (int kk = 0; kk < KCH; kk++) {
        if (kk < KCH - 1) CP_WAIT1(); else CP_WAIT0();
        __syncthreads();
        if (kk + 2 < KCH) {
            loadTile(k0 + kk + 2, nstage);
            CP_COMMIT();
        }
        const char* sb = smem_raw + stage * STAGE_B;
        const __nv_bfloat16* ah = (const __nv_bfloat16*)(sb + ST_AH);
        const __nv_bfloat16* al = (const __nv_bfloat16*)(sb + ST_AL);
        const __nv_bfloat16* bh = (const __nv_bfloat16*)(sb + ST_BH);
        const __nv_bfloat16* bl = (const __nv_bfloat16*)(sb + ST_BL);
#pragma unroll
        for (int ks = 0; ks < 2; ks++) {
            wmma::fragment<wmma::matrix_b, 16, 16, 16, __nv_bfloat16, wmma::row_major> fbh[2], fbl[2];
#pragma unroll
            for (int j = 0; j < 2; j++) {
                wmma::load_matrix_sync(fbh[j], bh + ks * 16 * LDB + warpN * 32 + j * 16, LDB);
                wmma::load_matrix_sync(fbl[j], bl + ks * 16 * LDB + warpN * 32 + j * 16, LDB);
            }
#pragma unroll
            for (int i = 0; i < 4; i++) {
                wmma::fragment<wmma::matrix_a, 16, 16, 16, __nv_bfloat16, wmma::row_major> fah, fal;
                wmma::load_matrix_sync(fah, ah + (warpM * 64 + i * 16) * LDA + ks * 16, LDA);
                wmma::load_matrix_sync(fal, al + (warpM * 64 + i * 16) * LDA + ks * 16, LDA);
#pragma unroll
                for (int j = 0; j < 2; j++) {
                    wmma::mma_sync(acc[i][j], fah, fbh[j], acc[i][j]);
                    wmma::mma_sync(acc[i][j], fah, fbl[j], acc[i][j]);
                    wmma::mma_sync(acc[i][j], fal, fbh[j], acc[i][j]);
                }
            }
        }
        stage = (stage + 1 == 3) ? 0 : stage + 1;
        nstage = (nstage + 1 == 3) ? 0 : nstage + 1;
    }
    __syncthreads();

    float* Stage = (float*)smem_raw;
#pragma unroll
    for (int i = 0; i < 4; i++)
#pragma unroll
        for (int j = 0; j < 2; j++)
            wmma::store_matrix_sync(Stage + (warpM * 64 + i * 16) * LDSTG + warpN * 32 + j * 16,
                                    acc[i][j], LDSTG, wmma::mem_row_major);
    __syncthreads();

    float* dst = g_part + ((size_t)(split * NMT + mtile) * NB + blockIdx.y) * (BM * BN);
#pragma unroll
    for (int it = 0; it < 16; it++) {
        int v = it * 256 + tid;
        int row = v >> 5, c4 = (v & 31) * 4;
        *(float4*)(dst + row * BN + c4) = *(const float4*)(Stage + row * LDSTG + c4);
    }
}

// conv1 epilogue: sum SPLITS1 partials + bias + relu -> X2 hi/lo (skip dummy rows)
__global__ void k_epi1(const float* __restrict__ bias) {
    const int mtile = blockIdx.x, nblk = blockIdx.y;
    const int col = threadIdx.x & 127, rh = threadIdx.x >> 7;
    const size_t tile_sz = (size_t)BM * BN;
    const size_t tb = ((size_t)mtile * 8 + nblk) * tile_sz;
    const float b = bias[nblk * 128 + col];
    for (int rr = rh * 64; rr < rh * 64 + 64; rr++) {
        int gi = mtile * BM + rr;
        if (gi >= VROWS1) break;
        int e = rr * BN + col;
        float v = 0.f;
#pragma unroll
        for (int s = 0; s < SPLITS1; s++)
            v += g_part[(size_t)s * NMT1 * 8 * tile_sz + tb + e];
        v = fmaxf(v + b, 0.f);
        __nv_bfloat16 hi, lo; split_bf16(v, hi, lo);
        size_t o = (size_t)(GUARD + padded_row1(gi)) * CH + nblk * 128 + col;
        g_X2h[o] = hi;
        g_X2l[o] = lo;
    }
}

// conv2 epilogue: sum SPLITS2 partials + bias + relu + maxpool -> g_pooled
__global__ void k_epi2(const float* __restrict__ bias) {
    const int mtile = blockIdx.x, nblk = blockIdx.y;
    const int col = threadIdx.x;  // 128 threads
    const size_t tile_sz = (size_t)BM * BN;
    const size_t tb = ((size_t)mtile * 4 + nblk) * tile_sz;
    const float* P0 = g_part + tb;
    const float* P1 = g_part + (size_t)NMT2 * 4 * tile_sz + tb;
    const float* P2 = g_part + (size_t)2 * NMT2 * 4 * tile_sz + tb;
    const float b = bias[nblk * 128 + col];
    float m = 0.f;
    int curt = (mtile * BM) / 784;
    for (int rr = 0; rr < BM; rr++) {
        int t = (mtile * BM + rr) / 784;
        if (t != curt) {
            atomicMax((int*)&g_pooled[curt * C2 + nblk * 128 + col], __float_as_int(m));
            m = 0.f;
            curt = t;
        }
        int e = rr * BN + col;
        m = fmaxf(m, P0[e] + P1[e] + P2[e] + b);
    }
    atomicMax((int*)&g_pooled[curt * C2 + nblk * 128 + col], __float_as_int(m));
}

// ---------------- tiny MLP ----------------
template<int IN, int OUT>
__global__ void k_fc(const float* __restrict__ W, const float* __restrict__ b,
                     const float* __restrict__ x, float* __restrict__ y) {
    int w = threadIdx.x >> 5, lane = threadIdx.x & 31;
    int o = blockIdx.x * 8 + w, t = blockIdx.y;
    float s = 0.f;
    for (int i = lane; i < IN; i += 32) s += x[t * IN + i] * W[(size_t)o * IN + i];
#pragma unroll
    for (int d = 16; d; d >>= 1) s += __shfl_down_sync(0xffffffffu, s, d);
    if (lane == 0) y[t * OUT + o] = fmaxf(s + b[o], 0.f);
}

extern "C" void kernel_launch(void* const* d_in, const int* in_sizes, int n_in,
                              void* d_out, int out_size) {
    const float* videos  = (const float*)d_in[0];
    const float* conv1_w = (const float*)d_in[1];
    const float* conv1_b = (const float*)d_in[2];
    const float* conv2_w = (const float*)d_in[3];
    const float* conv2_b = (const float*)d_in[4];
    const float* l1_w = (const float*)d_in[5];
    const float* l1_b = (const float*)d_in[6];
    const float* l2_w = (const float*)d_in[7];
    const float* l2_b = (const float*)d_in[8];
    const float* l3_w = (const float*)d_in[9];
    const float* l3_b = (const float*)d_in[10];
    float* out = (float*)d_out;

    auto g1 = k_gemm<CH, false, SPLITS1, NMT1, KCH1>;
    auto g2 = k_gemm<C2, true,  SPLITS2, NMT2, KCH2>;
    cudaFuncSetAttribute(g1, cudaFuncAttributeMaxDynamicSharedMemorySize, SMEM_BYTES);
    cudaFuncSetAttribute(g2, cudaFuncAttributeMaxDynamicSharedMemorySize, SMEM_BYTES);

    __nv_bfloat16 *w1th, *w1tl, *w2th, *w2tl;
    float *pooled, *m1, *m2;
    cudaGetSymbolAddress((void**)&w1th, g_W1Th);
    cudaGetSymbolAddress((void**)&w1tl, g_W1Tl);
    cudaGetSymbolAddress((void**)&w2th, g_W2Th);
    cudaGetSymbolAddress((void**)&w2tl, g_W2Tl);
    cudaGetSymbolAddress((void**)&pooled, g_pooled);
    cudaGetSymbolAddress((void**)&m1, g_m1);
    cudaGetSymbolAddress((void**)&m2, g_m2);

    constexpr int TOT = NWIN * 4 * 14 * 14 * CH;
    // Order: gather, t1, zero, g1 — g1 lands in ncu's profiled slot (-s 5 with
    // the harness's 2 internal pre-launches). t2/fill only needed before g2.
    k_gather<<<(TOT + 255) / 256, 256>>>(videos);
    k_transpose<CH><<<dim3(CH / 32, CH), 256>>>(conv1_w, w1th, w1tl);
    k_zero_pooled<<<(NWIN * C2 + 255) / 256, 256>>>();

    g1<<<dim3(NMT1, CH / BN, SPLITS1), 256, SMEM_BYTES>>>(0);

    k_transpose<C2><<<dim3(C2 / 32, CH), 256>>>(conv2_w, w2th, w2tl);
    k_fill<<<(7 * 196 * CH + 255) / 256, 256>>>(conv1_b);
    k_epi1<<<dim3(NMT1, CH / BN), 256>>>(conv1_b);

    g2<<<dim3(NMT2, C2 / BN, SPLITS2), 256, SMEM_BYTES>>>(0);
    k_epi2<<<dim3(NMT2, C2 / BN), 128>>>(conv2_b);

    k_fc<512, 512><<<dim3(64, NWIN), 256>>>(l1_w, l1_b, pooled, m1);
    k_fc<512, 512><<<dim3(64, NWIN), 256>>>(l2_w, l2_b, m1, m2);
    k_fc<512, 128><<<dim3(16, NWIN), 256>>>(l3_w, l3_b, m2, out);
}

// round 13
// speedup vs baseline: 4.4068x; 1.6099x over previous
#include <cuda_runtime.h>
#include <cuda_fp16.h>
#include <mma.h>
#include <cstdint>

using namespace nvcuda;

constexpr int NWIN = 8, CH = 1024, C2 = 512;
constexpr int SLAB = 256, WINSLABS = 6, GUARD = 256;
constexpr int ROWS_ALLOC = NWIN * WINSLABS * SLAB + 2 * GUARD;  // 12800
constexpr int KDIM = 27 * CH;                                    // 27648
constexpr int BM = 128, BN = 128, BK = 32;
constexpr int KCHUNKS = KDIM / BK;                               // 864

// conv1: 7 zero-partial slabs skipped -> 25 slabs * 196 = 4900 valid rows
constexpr int VROWS1 = 4900;
constexpr int NMT1 = 39;
constexpr int SPLITS1 = 16;
constexpr int KCH1 = KCHUNKS / SPLITS1;   // 54
// conv2: all 6272 rows
constexpr int VROWS2 = 6272;
constexpr int NMT2 = 49;
constexpr int SPLITS2 = 3;
constexpr int KCH2 = KCHUNKS / SPLITS2;   // 288

// bank-conflict-free smem strides (bytes ≡ 16 mod 32)
constexpr int LDA = 40;    // elements (80 B rows)
constexpr int LDB = 136;   // elements (272 B rows)
constexpr int LDSTG = 132; // fp32 staging stride

// 3-stage ring: per stage Ah, Al, B (B single fp16 version now)
constexpr int A_BUF = BM * LDA * 2;   // 10240 B
constexpr int B_BUF = BK * LDB * 2;   // 8704 B
constexpr int ST_AH = 0;
constexpr int ST_AL = A_BUF;
constexpr int ST_B  = 2 * A_BUF;
constexpr int STAGE_B = 2 * A_BUF + B_BUF;  // 29184
constexpr int SMEM_BYTES = 3 * STAGE_B;     // 87552 (2 CTAs/SM)

__device__ __half g_X1h[(size_t)ROWS_ALLOC * CH];
__device__ __half g_X1l[(size_t)ROWS_ALLOC * CH];
__device__ __half g_X2h[(size_t)ROWS_ALLOC * CH];
__device__ __half g_X2l[(size_t)ROWS_ALLOC * CH];
__device__ __half g_W1T[(size_t)KDIM * CH];   // [kidx*CH+ic][oc], fp16
__device__ __half g_W2T[(size_t)KDIM * C2];
// partials: conv1 needs SPLITS1*NMT1*8 = 4992 tiles; conv2 reuses (588 tiles)
__device__ float g_part[(size_t)SPLITS1 * NMT1 * 8 * BM * BN];
__device__ float g_pooled[NWIN * C2];
__device__ float g_m1[NWIN * 512];
__device__ float g_m2[NWIN * 512];

__device__ __forceinline__ void split_fp16(float v, __half& hi, __half& lo) {
    hi = __float2half(v);
    lo = __float2half(v - __half2float(hi));
}

// conv2 valid-row index (all 32 slabs) -> padded row
__device__ __forceinline__ int padded_row2(int i) {
    int t = i / 784, rem = i - t * 784;
    int d = rem / 196, s = rem - d * 196;
    int h = s / 14, w = s - h * 14;
    return (t * WINSLABS + d + 1) * SLAB + (h + 1) * 16 + (w + 1);
}

// conv1 compacted-row index (25 nonzero slabs) -> padded row; dummy rows -> 273 (safe)
__device__ __forceinline__ int padded_row1(int i) {
    if (i >= VROWS1) return 273;
    int s = i / 196, pos = i - s * 196;
    int t, d;
    if (s < 2)      { t = 1; d = s + 2; }
    else if (s < 5) { t = 2; d = s - 1; }
    else            { int q = s - 5; t = 3 + (q >> 2); d = q & 3; }
    int h = pos / 14, w = pos - h * 14;
    return (t * WINSLABS + d + 1) * SLAB + (h + 1) * 16 + (w + 1);
}

__device__ __forceinline__ uint32_t smem_u32(const void* p) {
    uint32_t a;
    asm("{ .reg .u64 t; cvta.to.shared.u64 t, %1; cvt.u32.u64 %0, t; }" : "=r"(a) : "l"(p));
    return a;
}
#define CP_ASYNC16(dst, src) \
    asm volatile("cp.async.cg.shared.global [%0], [%1], 16;" :: "r"(dst), "l"(src))
#define CP_COMMIT() asm volatile("cp.async.commit_group;" ::: "memory")
#define CP_WAIT0()  asm volatile("cp.async.wait_group 0;" ::: "memory")
#define CP_WAIT1()  asm volatile("cp.async.wait_group 1;" ::: "memory")

// ---------------- prep kernels ----------------
__global__ void k_zero_pooled() {
    int i = blockIdx.x * 256 + threadIdx.x;
    if (i < NWIN * C2) g_pooled[i] = 0.f;
}

__global__ void k_gather(const float* __restrict__ videos) {
    int i = blockIdx.x * 256 + threadIdx.x;
    constexpr int TOT = NWIN * 4 * 14 * 14 * CH;
    if (i >= TOT) return;
    int c = i & (CH - 1);
    int rest = i >> 10;
    int w = rest % 14; rest /= 14;
    int h = rest % 14; rest /= 14;
    int d = rest & 3;
    int t = rest >> 2;
    int frame = t - 4 + d;  // window t holds frames t-4..t-1 (zeros before 0)
    float v = (frame >= 0) ? videos[(size_t)(frame * CH + c) * 196 + h * 14 + w] : 0.f;
    __half hi, lo; split_fp16(v, hi, lo);
    size_t dst = (size_t)(GUARD + (t * WINSLABS + d + 1) * SLAB + (h + 1) * 16 + (w + 1)) * CH + c;
    g_X1h[dst] = hi;
    g_X1l[dst] = lo;
}

// fill the 7 all-zero-input conv1 output slabs with relu(b1)
__global__ void k_fill(const float* __restrict__ b1) {
    int i = blockIdx.x * 256 + threadIdx.x;
    constexpr int TOT = 7 * 196 * CH;
    if (i >= TOT) return;
    int c = i & (CH - 1);
    int rest = i >> 10;
    int s2 = rest / 196, pos = rest - s2 * 196;
    int t = (s2 < 4) ? 0 : (s2 < 6) ? 1 : 2;
    int d = (s2 < 4) ? s2 : (s2 < 6) ? s2 - 4 : 0;
    int h = pos / 14, w = pos - h * 14;
    float v = fmaxf(b1[c], 0.f);
    __half hi, lo; split_fp16(v, hi, lo);
    size_t o = (size_t)(GUARD + (t * WINSLABS + d + 1) * SLAB + (h + 1) * 16 + (w + 1)) * CH + c;
    g_X2h[o] = hi;
    g_X2l[o] = lo;
}

// conv weights (oc, ic, 27) -> WT[kidx*CH+ic][oc], single fp16
template<int NOC>
__global__ void k_transpose(const float* __restrict__ w, __half* __restrict__ wt) {
    __shared__ float s[32][28];
    int ocBase = blockIdx.x * 32;
    int ic = blockIdx.y;
    for (int idx = threadIdx.x; idx < 32 * 27; idx += 256) {
        int oc = idx / 27, kk = idx - oc * 27;
        s[oc][kk] = w[((size_t)(ocBase + oc) * CH + ic) * 27 + kk];
    }
    __syncthreads();
    for (int idx = threadIdx.x; idx < 27 * 32; idx += 256) {
        int kk = idx >> 5, oc = idx & 31;
        wt[((size_t)kk * CH + ic) * NOC + ocBase + oc] = __float2half(s[oc][kk]);
    }
}

// ---- implicit-conv GEMM: fp16 2-term (exact-A x fp16-B), split-K, 3-stage ----
template<int N, bool L2, int SPL, int NMT, int KCH>
__global__ void __launch_bounds__(256, 2)
k_gemm(int dummy) {
    const __half* __restrict__ Xh = (L2 ? g_X2h : g_X1h) + (size_t)GUARD * CH;
    const __half* __restrict__ Xl = (L2 ? g_X2l : g_X1l) + (size_t)GUARD * CH;
    const __half* __restrict__ W  = L2 ? g_W2T : g_W1T;
    constexpr int NB = N / BN;

    extern __shared__ __align__(128) char smem_raw[];
    const uint32_t sbase = smem_u32(smem_raw);

    const int tid = threadIdx.x;
    const int mtile = blockIdx.x;
    const int nBase = blockIdx.y * BN;
    const int split = blockIdx.z;
    const int k0 = split * KCH;

    const int r0 = tid >> 2;
    const long pr0 = L2 ? padded_row2(mtile * BM + r0)      : padded_row1(mtile * BM + r0);
    const long pr1 = L2 ? padded_row2(mtile * BM + r0 + 64) : padded_row1(mtile * BM + r0 + 64);
    const int ac = (tid & 3) * 8;

    wmma::fragment<wmma::accumulator, 16, 16, 16, float> acc[4][2];
#pragma unroll
    for (int i = 0; i < 4; i++)
#pragma unroll
        for (int j = 0; j < 2; j++) wmma::fill_fragment(acc[i][j], 0.f);

    const int warpId = tid >> 5;
    const int warpM = warpId >> 2;
    const int warpN = warpId & 3;

    auto loadTile = [&](int kt, int stage) {
        const int kidx = kt >> 5;
        const int icBase = (kt & 31) << 5;
        const int kd = kidx / 9, r9 = kidx - kd * 9;
        const int kh = r9 / 3, kw = r9 - kh * 3;
        const long off = (long)(kd - 1) * SLAB + (kh - 1) * 16 + (kw - 1);
        const uint32_t sb = sbase + stage * STAGE_B;
#pragma unroll
        for (int it = 0; it < 2; it++) {
            const long so = ((it ? pr1 : pr0) + off) * CH + icBase + ac;
            const uint32_t do_ = (r0 + it * 64) * (LDA * 2) + (ac * 2);
            CP_ASYNC16(sb + ST_AH + do_, Xh + so);
            CP_ASYNC16(sb + ST_AL + do_, Xl + so);
        }
        const size_t wb = (size_t)kt * BK * N + nBase;
#pragma unroll
        for (int it = 0; it < 2; it++) {
            int v = it * 256 + tid;
            int row = v >> 4, c = v & 15;
            CP_ASYNC16(sb + ST_B + row * (LDB * 2) + c * 16, W + wb + (size_t)row * N + c * 8);
        }
    };

    loadTile(k0, 0);     CP_COMMIT();
    loadTile(k0 + 1, 1); CP_COMMIT();

    int stage = 0, nstage = 2;
    for (int kk = 0; kk < KCH; kk++) {
        if (kk < KCH - 1) CP_WAIT1(); else CP_WAIT0();
        __syncthreads();
        if (kk + 2 < KCH) {
            loadTile(k0 + kk + 2, nstage);
            CP_COMMIT();
        }
        const char* sb = smem_raw + stage * STAGE_B;
        const __half* ah = (const __half*)(sb + ST_AH);
        const __half* al = (const __half*)(sb + ST_AL);
        const __half* bb = (const __half*)(sb + ST_B);
#pragma unroll
        for (int ks = 0; ks < 2; ks++) {
            wmma::fragment<wmma::matrix_b, 16, 16, 16, __half, wmma::row_major> fb[2];
#pragma unroll
            for (int j = 0; j < 2; j++)
                wmma::load_matrix_sync(fb[j], bb + ks * 16 * LDB + warpN * 32 + j * 16, LDB);
#pragma unroll
            for (int i = 0; i < 4; i++) {
                wmma::fragment<wmma::matrix_a, 16, 16, 16, __half, wmma::row_major> fah, fal;
                wmma::load_matrix_sync(fah, ah + (warpM * 64 + i * 16) * LDA + ks * 16, LDA);
                wmma::load_matrix_sync(fal, al + (warpM * 64 + i * 16) * LDA + ks * 16, LDA);
#pragma unroll
                for (int j = 0; j < 2; j++) {
                    wmma::mma_sync(acc[i][j], fah, fb[j], acc[i][j]);
                    wmma::mma_sync(acc[i][j], fal, fb[j], acc[i][j]);
                }
            }
        }
        stage = (stage + 1 == 3) ? 0 : stage + 1;
        nstage = (nstage + 1 == 3) ? 0 : nstage + 1;
    }
    __syncthreads();

    float* Stage = (float*)smem_raw;   // 128 x 132 fp32 = 67584 <= 87552
#pragma unroll
    for (int i = 0; i < 4; i++)
#pragma unroll
        for (int j = 0; j < 2; j++)
            wmma::store_matrix_sync(Stage + (warpM * 64 + i * 16) * LDSTG + warpN * 32 + j * 16,
                                    acc[i][j], LDSTG, wmma::mem_row_major);
    __syncthreads();

    float* dst = g_part + ((size_t)(split * NMT + mtile) * NB + blockIdx.y) * (BM * BN);
#pragma unroll
    for (int it = 0; it < 16; it++) {
        int v = it * 256 + tid;
        int row = v >> 5, c4 = (v & 31) * 4;
        *(float4*)(dst + row * BN + c4) = *(const float4*)(Stage + row * LDSTG + c4);
    }
}

// conv1 epilogue: sum SPLITS1 partials + bias + relu -> X2 hi/lo (skip dummy rows)
__global__ void k_epi1(const float* __restrict__ bias) {
    const int mtile = blockIdx.x, nblk = blockIdx.y;
    const int col = threadIdx.x & 127, rh = threadIdx.x >> 7;
    const size_t tile_sz = (size_t)BM * BN;
    const size_t tb = ((size_t)mtile * 8 + nblk) * tile_sz;
    const float b = bias[nblk * 128 + col];
    for (int rr = rh * 64; rr < rh * 64 + 64; rr++) {
        int gi = mtile * BM + rr;
        if (gi >= VROWS1) break;
        int e = rr * BN + col;
        float v = 0.f;
#pragma unroll
        for (int s = 0; s < SPLITS1; s++)
            v += g_part[(size_t)s * NMT1 * 8 * tile_sz + tb + e];
        v = fmaxf(v + b, 0.f);
        __half hi, lo; split_fp16(v, hi, lo);
        size_t o = (size_t)(GUARD + padded_row1(gi)) * CH + nblk * 128 + col;
        g_X2h[o] = hi;
        g_X2l[o] = lo;
    }
}

// conv2 epilogue: sum SPLITS2 partials + bias + relu + maxpool -> g_pooled
__global__ void k_epi2(const float* __restrict__ bias) {
    const int mtile = blockIdx.x, nblk = blockIdx.y;
    const int col = threadIdx.x;  // 128 threads
    const size_t tile_sz = (size_t)BM * BN;
    const size_t tb = ((size_t)mtile * 4 + nblk) * tile_sz;
    const float* P0 = g_part + tb;
    const float* P1 = g_part + (size_t)NMT2 * 4 * tile_sz + tb;
    const float* P2 = g_part + (size_t)2 * NMT2 * 4 * tile_sz + tb;
    const float b = bias[nblk * 128 + col];
    float m = 0.f;
    int curt = (mtile * BM) / 784;
    for (int rr = 0; rr < BM; rr++) {
        int t = (mtile * BM + rr) / 784;
        if (t != curt) {
            atomicMax((int*)&g_pooled[curt * C2 + nblk * 128 + col], __float_as_int(m));
            m = 0.f;
            curt = t;
        }
        int e = rr * BN + col;
        m = fmaxf(m, P0[e] + P1[e] + P2[e] + b);
    }
    atomicMax((int*)&g_pooled[curt * C2 + nblk * 128 + col], __float_as_int(m));
}

// ---------------- tiny MLP ----------------
template<int IN, int OUT>
__global__ void k_fc(const float* __restrict__ W, const float* __restrict__ b,
                     const float* __restrict__ x, float* __restrict__ y) {
    int w = threadIdx.x >> 5, lane = threadIdx.x & 31;
    int o = blockIdx.x * 8 + w, t = blockIdx.y;
    float s = 0.f;
    for (int i = lane; i < IN; i += 32) s += x[t * IN + i] * W[(size_t)o * IN + i];
#pragma unroll
    for (int d = 16; d; d >>= 1) s += __shfl_down_sync(0xffffffffu, s, d);
    if (lane == 0) y[t * OUT + o] = fmaxf(s + b[o], 0.f);
}

extern "C" void kernel_launch(void* const* d_in, const int* in_sizes, int n_in,
                              void* d_out, int out_size) {
    const float* videos  = (const float*)d_in[0];
    const float* conv1_w = (const float*)d_in[1];
    const float* conv1_b = (const float*)d_in[2];
    const float* conv2_w = (const float*)d_in[3];
    const float* conv2_b = (const float*)d_in[4];
    const float* l1_w = (const float*)d_in[5];
    const float* l1_b = (const float*)d_in[6];
    const float* l2_w = (const float*)d_in[7];
    const float* l2_b = (const float*)d_in[8];
    const float* l3_w = (const float*)d_in[9];
    const float* l3_b = (const float*)d_in[10];
    float* out = (float*)d_out;

    auto g1 = k_gemm<CH, false, SPLITS1, NMT1, KCH1>;
    auto g2 = k_gemm<C2, true,  SPLITS2, NMT2, KCH2>;
    cudaFuncSetAttribute(g1, cudaFuncAttributeMaxDynamicSharedMemorySize, SMEM_BYTES);
    cudaFuncSetAttribute(g2, cudaFuncAttributeMaxDynamicSharedMemorySize, SMEM_BYTES);

    __half *w1t, *w2t;
    float *pooled, *m1, *m2;
    cudaGetSymbolAddress((void**)&w1t, g_W1T);
    cudaGetSymbolAddress((void**)&w2t, g_W2T);
    cudaGetSymbolAddress((void**)&pooled, g_pooled);
    cudaGetSymbolAddress((void**)&m1, g_m1);
    cudaGetSymbolAddress((void**)&m2, g_m2);

    constexpr int TOT = NWIN * 4 * 14 * 14 * CH;
    // g1 in the ncu-profiled slot (4th launch)
    k_gather<<<(TOT + 255) / 256, 256>>>(videos);
    k_transpose<CH><<<dim3(CH / 32, CH), 256>>>(conv1_w, w1t);
    k_zero_pooled<<<(NWIN * C2 + 255) / 256, 256>>>();

    g1<<<dim3(NMT1, CH / BN, SPLITS1), 256, SMEM_BYTES>>>(0);

    k_transpose<C2><<<dim3(C2 / 32, CH), 256>>>(conv2_w, w2t);
    k_fill<<<(7 * 196 * CH + 255) / 256, 256>>>(conv1_b);
    k_epi1<<<dim3(NMT1, CH / BN), 256>>>(conv1_b);

    g2<<<dim3(NMT2, C2 / BN, SPLITS2), 256, SMEM_BYTES>>>(0);
    k_epi2<<<dim3(NMT2, C2 / BN), 128>>>(conv2_b);

    k_fc<512, 512><<<dim3(64, NWIN), 256>>>(l1_w, l1_b, pooled, m1);
    k_fc<512, 512><<<dim3(64, NWIN), 256>>>(l2_w, l2_b, m1, m2);
    k_fc<512, 128><<<dim3(16, NWIN), 256>>>(l3_w, l3_b, m2, out);
}

// round 14
// speedup vs baseline: 7.0043x; 1.5894x over previous
#include <cuda_runtime.h>
#include <cuda_fp16.h>
#include <mma.h>
#include <cstdint>

using namespace nvcuda;

constexpr int NWIN = 8, CH = 1024, C2 = 512;
constexpr int SLAB = 256, WINSLABS = 6, GUARD = 256;
constexpr int ROWS_ALLOC = NWIN * WINSLABS * SLAB + 2 * GUARD;  // 12800
constexpr int KDIM = 27 * CH;                                    // 27648
constexpr int BM = 128, BN = 128, BK = 32;
constexpr int KCHUNKS = KDIM / BK;                               // 864

// conv1: 7 zero-partial slabs skipped -> 25 slabs * 196 = 4900 valid rows
constexpr int VROWS1 = 4900;
constexpr int NMT1 = 39;
constexpr int SPLITS1 = 16;
constexpr int KCH1 = KCHUNKS / SPLITS1;   // 54
// conv2: all 6272 rows
constexpr int VROWS2 = 6272;
constexpr int NMT2 = 49;
constexpr int SPLITS2 = 3;
constexpr int KCH2 = KCHUNKS / SPLITS2;   // 288

// bank-conflict-free smem strides (bytes ≡ 16 mod 32)
constexpr int LDA = 40;    // elements (80 B rows)
constexpr int LDB = 136;   // elements (272 B rows)
constexpr int LDSTG = 132; // fp32 staging stride

// 3-stage ring: per stage A, B (single fp16 versions)
constexpr int A_BUF = BM * LDA * 2;   // 10240 B
constexpr int B_BUF = BK * LDB * 2;   // 8704 B
constexpr int ST_A = 0;
constexpr int ST_B = A_BUF;
constexpr int STAGE_B = A_BUF + B_BUF;   // 18944
constexpr int SMEM_BYTES = 3 * STAGE_B;  // 56832 (2 CTAs/SM, reg-limited)

__device__ __half g_X1[(size_t)ROWS_ALLOC * CH];
__device__ __half g_X2[(size_t)ROWS_ALLOC * CH];
__device__ __half g_W1T[(size_t)KDIM * CH];   // [kidx*CH+ic][oc], fp16
__device__ __half g_W2T[(size_t)KDIM * C2];
// partials: conv1 needs SPLITS1*NMT1*8 = 4992 tiles; conv2 reuses (588 tiles)
__device__ float g_part[(size_t)SPLITS1 * NMT1 * 8 * BM * BN];
__device__ float g_pooled[NWIN * C2];
__device__ float g_m1[NWIN * 512];
__device__ float g_m2[NWIN * 512];

// conv2 valid-row index (all 32 slabs) -> padded row
__device__ __forceinline__ int padded_row2(int i) {
    int t = i / 784, rem = i - t * 784;
    int d = rem / 196, s = rem - d * 196;
    int h = s / 14, w = s - h * 14;
    return (t * WINSLABS + d + 1) * SLAB + (h + 1) * 16 + (w + 1);
}

// conv1 compacted-row index (25 nonzero slabs) -> padded row; dummy rows -> 273 (safe)
__device__ __forceinline__ int padded_row1(int i) {
    if (i >= VROWS1) return 273;
    int s = i / 196, pos = i - s * 196;
    int t, d;
    if (s < 2)      { t = 1; d = s + 2; }
    else if (s < 5) { t = 2; d = s - 1; }
    else            { int q = s - 5; t = 3 + (q >> 2); d = q & 3; }
    int h = pos / 14, w = pos - h * 14;
    return (t * WINSLABS + d + 1) * SLAB + (h + 1) * 16 + (w + 1);
}

__device__ __forceinline__ uint32_t smem_u32(const void* p) {
    uint32_t a;
    asm("{ .reg .u64 t; cvta.to.shared.u64 t, %1; cvt.u32.u64 %0, t; }" : "=r"(a) : "l"(p));
    return a;
}
#define CP_ASYNC16(dst, src) \
    asm volatile("cp.async.cg.shared.global [%0], [%1], 16;" :: "r"(dst), "l"(src))
#define CP_COMMIT() asm volatile("cp.async.commit_group;" ::: "memory")
#define CP_WAIT0()  asm volatile("cp.async.wait_group 0;" ::: "memory")
#define CP_WAIT1()  asm volatile("cp.async.wait_group 1;" ::: "memory")

// ---------------- prep kernels ----------------
__global__ void k_zero_pooled() {
    int i = blockIdx.x * 256 + threadIdx.x;
    if (i < NWIN * C2) g_pooled[i] = 0.f;
}

__global__ void k_gather(const float* __restrict__ videos) {
    int i = blockIdx.x * 256 + threadIdx.x;
    constexpr int TOT = NWIN * 4 * 14 * 14 * CH;
    if (i >= TOT) return;
    int c = i & (CH - 1);
    int rest = i >> 10;
    int w = rest % 14; rest /= 14;
    int h = rest % 14; rest /= 14;
    int d = rest & 3;
    int t = rest >> 2;
    int frame = t - 4 + d;  // window t holds frames t-4..t-1 (zeros before 0)
    float v = (frame >= 0) ? videos[(size_t)(frame * CH + c) * 196 + h * 14 + w] : 0.f;
    size_t dst = (size_t)(GUARD + (t * WINSLABS + d + 1) * SLAB + (h + 1) * 16 + (w + 1)) * CH + c;
    g_X1[dst] = __float2half(v);
}

// fill the 7 all-zero-input conv1 output slabs with relu(b1)
__global__ void k_fill(const float* __restrict__ b1) {
    int i = blockIdx.x * 256 + threadIdx.x;
    constexpr int TOT = 7 * 196 * CH;
    if (i >= TOT) return;
    int c = i & (CH - 1);
    int rest = i >> 10;
    int s2 = rest / 196, pos = rest - s2 * 196;
    int t = (s2 < 4) ? 0 : (s2 < 6) ? 1 : 2;
    int d = (s2 < 4) ? s2 : (s2 < 6) ? s2 - 4 : 0;
    int h = pos / 14, w = pos - h * 14;
    size_t o = (size_t)(GUARD + (t * WINSLABS + d + 1) * SLAB + (h + 1) * 16 + (w + 1)) * CH + c;
    g_X2[o] = __float2half(fmaxf(b1[c], 0.f));
}

// conv weights (oc, ic, 27) -> WT[kidx*CH+ic][oc], fp16
template<int NOC>
__global__ void k_transpose(const float* __restrict__ w, __half* __restrict__ wt) {
    __shared__ float s[32][28];
    int ocBase = blockIdx.x * 32;
    int ic = blockIdx.y;
    for (int idx = threadIdx.x; idx < 32 * 27; idx += 256) {
        int oc = idx / 27, kk = idx - oc * 27;
        s[oc][kk] = w[((size_t)(ocBase + oc) * CH + ic) * 27 + kk];
    }
    __syncthreads();
    for (int idx = threadIdx.x; idx < 27 * 32; idx += 256) {
        int kk = idx >> 5, oc = idx & 31;
        wt[((size_t)kk * CH + ic) * NOC + ocBase + oc] = __float2half(s[oc][kk]);
    }
}

// ---- implicit-conv GEMM: single-term fp16, split-K, 3-stage cp.async ----
template<int N, bool L2, int SPL, int NMT, int KCH>
__global__ void __launch_bounds__(256, 2)
k_gemm(int dummy) {
    const __half* __restrict__ X = (L2 ? g_X2 : g_X1) + (size_t)GUARD * CH;
    const __half* __restrict__ W = L2 ? g_W2T : g_W1T;
    constexpr int NB = N / BN;

    extern __shared__ __align__(128) char smem_raw[];
    const uint32_t sbase = smem_u32(smem_raw);

    const int tid = threadIdx.x;
    const int mtile = blockIdx.x;
    const int nBase = blockIdx.y * BN;
    const int split = blockIdx.z;
    const int k0 = split * KCH;

    const int r0 = tid >> 2;
    const long pr0 = L2 ? padded_row2(mtile * BM + r0)      : padded_row1(mtile * BM + r0);
    const long pr1 = L2 ? padded_row2(mtile * BM + r0 + 64) : padded_row1(mtile * BM + r0 + 64);
    const int ac = (tid & 3) * 8;

    wmma::fragment<wmma::accumulator, 16, 16, 16, float> acc[4][2];
#pragma unroll
    for (int i = 0; i < 4; i++)
#pragma unroll
        for (int j = 0; j < 2; j++) wmma::fill_fragment(acc[i][j], 0.f);

    const int warpId = tid >> 5;
    const int warpM = warpId >> 2;
    const int warpN = warpId & 3;

    auto loadTile = [&](int kt, int stage) {
        const int kidx = kt >> 5;
        const int icBase = (kt & 31) << 5;
        const int kd = kidx / 9, r9 = kidx - kd * 9;
        const int kh = r9 / 3, kw = r9 - kh * 3;
        const long off = (long)(kd - 1) * SLAB + (kh - 1) * 16 + (kw - 1);
        const uint32_t sb = sbase + stage * STAGE_B;
#pragma unroll
        for (int it = 0; it < 2; it++) {
            const long so = ((it ? pr1 : pr0) + off) * CH + icBase + ac;
            CP_ASYNC16(sb + ST_A + (r0 + it * 64) * (LDA * 2) + ac * 2, X + so);
        }
        const size_t wb = (size_t)kt * BK * N + nBase;
#pragma unroll
        for (int it = 0; it < 2; it++) {
            int v = it * 256 + tid;
            int row = v >> 4, c = v & 15;
            CP_ASYNC16(sb + ST_B + row * (LDB * 2) + c * 16, W + wb + (size_t)row * N + c * 8);
        }
    };

    loadTile(k0, 0);     CP_COMMIT();
    loadTile(k0 + 1, 1); CP_COMMIT();

    int stage = 0, nstage = 2;
    for (int kk = 0; kk < KCH; kk++) {
        if (kk < KCH - 1) CP_WAIT1(); else CP_WAIT0();
        __syncthreads();
        if (kk + 2 < KCH) {
            loadTile(k0 + kk + 2, nstage);
            CP_COMMIT();
        }
        const char* sb = smem_raw + stage * STAGE_B;
        const __half* aa = (const __half*)(sb + ST_A);
        const __half* bb = (const __half*)(sb + ST_B);
#pragma unroll
        for (int ks = 0; ks < 2; ks++) {
            wmma::fragment<wmma::matrix_b, 16, 16, 16, __half, wmma::row_major> fb[2];
#pragma unroll
            for (int j = 0; j < 2; j++)
                wmma::load_matrix_sync(fb[j], bb + ks * 16 * LDB + warpN * 32 + j * 16, LDB);
#pragma unroll
            for (int i = 0; i < 4; i++) {
                wmma::fragment<wmma::matrix_a, 16, 16, 16, __half, wmma::row_major> fa;
                wmma::load_matrix_sync(fa, aa + (warpM * 64 + i * 16) * LDA + ks * 16, LDA);
#pragma unroll
                for (int j = 0; j < 2; j++)
                    wmma::mma_sync(acc[i][j], fa, fb[j], acc[i][j]);
            }
        }
        stage = (stage + 1 == 3) ? 0 : stage + 1;
        nstage = (nstage + 1 == 3) ? 0 : nstage + 1;
    }
    __syncthreads();

    float* Stage = (float*)smem_raw;   // needs 67584 B... exceeds 56832 -> stage in halves
    // store upper 64 rows, write, then lower 64 rows
#pragma unroll
    for (int half = 0; half < 2; half++) {
        if (warpM == half) {
#pragma unroll
            for (int i = 0; i < 4; i++)
#pragma unroll
                for (int j = 0; j < 2; j++)
                    wmma::store_matrix_sync(Stage + (i * 16) * LDSTG + warpN * 32 + j * 16,
                                            acc[i][j], LDSTG, wmma::mem_row_major);
        }
        __syncthreads();
        float* dst = g_part + ((size_t)(split * NMT + mtile) * NB + blockIdx.y) * (BM * BN)
                   + (size_t)half * 64 * BN;
#pragma unroll
        for (int it = 0; it < 8; it++) {
            int v = it * 256 + tid;
            int row = v >> 5, c4 = (v & 31) * 4;
            *(float4*)(dst + row * BN + c4) = *(const float4*)(Stage + row * LDSTG + c4);
        }
        __syncthreads();
    }
}

// conv1 epilogue: sum SPLITS1 partials + bias + relu -> X2 fp16 (skip dummy rows)
__global__ void k_epi1(const float* __restrict__ bias) {
    const int mtile = blockIdx.x, nblk = blockIdx.y;
    const int col = threadIdx.x & 127, rh = threadIdx.x >> 7;
    const size_t tile_sz = (size_t)BM * BN;
    const size_t tb = ((size_t)mtile * 8 + nblk) * tile_sz;
    const float b = bias[nblk * 128 + col];
    for (int rr = rh * 64; rr < rh * 64 + 64; rr++) {
        int gi = mtile * BM + rr;
        if (gi >= VROWS1) break;
        int e = rr * BN + col;
        float v = 0.f;
#pragma unroll
        for (int s = 0; s < SPLITS1; s++)
            v += g_part[(size_t)s * NMT1 * 8 * tile_sz + tb + e];
        v = fmaxf(v + b, 0.f);
        size_t o = (size_t)(GUARD + padded_row1(gi)) * CH + nblk * 128 + col;
        g_X2[o] = __float2half(v);
    }
}

// conv2 epilogue: sum SPLITS2 partials + bias + relu + maxpool -> g_pooled
__global__ void k_epi2(const float* __restrict__ bias) {
    const int mtile = blockIdx.x, nblk = blockIdx.y;
    const int col = threadIdx.x;  // 128 threads
    const size_t tile_sz = (size_t)BM * BN;
    const size_t tb = ((size_t)mtile * 4 + nblk) * tile_sz;
    const float* P0 = g_part + tb;
    const float* P1 = g_part + (size_t)NMT2 * 4 * tile_sz + tb;
    const float* P2 = g_part + (size_t)2 * NMT2 * 4 * tile_sz + tb;
    const float b = bias[nblk * 128 + col];
    float m = 0.f;
    int curt = (mtile * BM) / 784;
    for (int rr = 0; rr < BM; rr++) {
        int t = (mtile * BM + rr) / 784;
        if (t != curt) {
            atomicMax((int*)&g_pooled[curt * C2 + nblk * 128 + col], __float_as_int(m));
            m = 0.f;
            curt = t;
        }
        int e = rr * BN + col;
        m = fmaxf(m, P0[e] + P1[e] + P2[e] + b);
    }
    atomicMax((int*)&g_pooled[curt * C2 + nblk * 128 + col], __float_as_int(m));
}

// ---------------- tiny MLP ----------------
template<int IN, int OUT>
__global__ void k_fc(const float* __restrict__ W, const float* __restrict__ b,
                     const float* __restrict__ x, float* __restrict__ y) {
    int w = threadIdx.x >> 5, lane = threadIdx.x & 31;
    int o = blockIdx.x * 8 + w, t = blockIdx.y;
    float s = 0.f;
    for (int i = lane; i < IN; i += 32) s += x[t * IN + i] * W[(size_t)o * IN + i];
#pragma unroll
    for (int d = 16; d; d >>= 1) s += __shfl_down_sync(0xffffffffu, s, d);
    if (lane == 0) y[t * OUT + o] = fmaxf(s + b[o], 0.f);
}

extern "C" void kernel_launch(void* const* d_in, const int* in_sizes, int n_in,
                              void* d_out, int out_size) {
    const float* videos  = (const float*)d_in[0];
    const float* conv1_w = (const float*)d_in[1];
    const float* conv1_b = (const float*)d_in[2];
    const float* conv2_w = (const float*)d_in[3];
    const float* conv2_b = (const float*)d_in[4];
    const float* l1_w = (const float*)d_in[5];
    const float* l1_b = (const float*)d_in[6];
    const float* l2_w = (const float*)d_in[7];
    const float* l2_b = (const float*)d_in[8];
    const float* l3_w = (const float*)d_in[9];
    const float* l3_b = (const float*)d_in[10];
    float* out = (float*)d_out;

    auto g1 = k_gemm<CH, false, SPLITS1, NMT1, KCH1>;
    auto g2 = k_gemm<C2, true,  SPLITS2, NMT2, KCH2>;
    cudaFuncSetAttribute(g1, cudaFuncAttributeMaxDynamicSharedMemorySize, SMEM_BYTES);
    cudaFuncSetAttribute(g2, cudaFuncAttributeMaxDynamicSharedMemorySize, SMEM_BYTES);

    __half *w1t, *w2t;
    float *pooled, *m1, *m2;
    cudaGetSymbolAddress((void**)&w1t, g_W1T);
    cudaGetSymbolAddress((void**)&w2t, g_W2T);
    cudaGetSymbolAddress((void**)&pooled, g_pooled);
    cudaGetSymbolAddress((void**)&m1, g_m1);
    cudaGetSymbolAddress((void**)&m2, g_m2);

    constexpr int TOT = NWIN * 4 * 14 * 14 * CH;
    // g1 in the ncu-profiled slot (4th launch)
    k_gather<<<(TOT + 255) / 256, 256>>>(videos);
    k_transpose<CH><<<dim3(CH / 32, CH), 256>>>(conv1_w, w1t);
    k_zero_pooled<<<(NWIN * C2 + 255) / 256, 256>>>();

    g1<<<dim3(NMT1, CH / BN, SPLITS1), 256, SMEM_BYTES>>>(0);

    k_transpose<C2><<<dim3(C2 / 32, CH), 256>>>(conv2_w, w2t);
    k_fill<<<(7 * 196 * CH + 255) / 256, 256>>>(conv1_b);
    k_epi1<<<dim3(NMT1, CH / BN), 256>>>(conv1_b);

    g2<<<dim3(NMT2, C2 / BN, SPLITS2), 256, SMEM_BYTES>>>(0);
    k_epi2<<<dim3(NMT2, C2 / BN), 128>>>(conv2_b);

    k_fc<512, 512><<<dim3(64, NWIN), 256>>>(l1_w, l1_b, pooled, m1);
    k_fc<512, 512><<<dim3(64, NWIN), 256>>>(l2_w, l2_b, m1, m2);
    k_fc<512, 128><<<dim3(16, NWIN), 256>>>(l3_w, l3_b, m2, out);
}

// round 15
// speedup vs baseline: 7.6977x; 1.0990x over previous
#include <cuda_runtime.h>
#include <cuda_fp16.h>
#include <mma.h>
#include <cstdint>

using namespace nvcuda;

constexpr int NWIN = 8, CH = 1024, C2 = 512;
constexpr int SLAB = 256, WINSLABS = 6, GUARD = 256;
constexpr int ROWS_ALLOC = NWIN * WINSLABS * SLAB + 2 * GUARD;  // 12800
constexpr int KDIM = 27 * CH;                                    // 27648
constexpr int BM = 128, BN = 128, BK = 64;
constexpr int KCHUNKS = KDIM / BK;                               // 432 (16 ic-blocks/tap)

// conv1: 7 zero-partial slabs skipped -> 4900 valid rows
constexpr int VROWS1 = 4900;
constexpr int NMT1 = 39;
constexpr int SPLITS1 = 16;
constexpr int KCH1 = KCHUNKS / SPLITS1;   // 27
// conv2: all 6272 rows
constexpr int VROWS2 = 6272;
constexpr int NMT2 = 49;
constexpr int SPLITS2 = 3;
constexpr int KCH2 = KCHUNKS / SPLITS2;   // 144

// ldmatrix conflict-free strides: (stride/16) odd
constexpr int LDA = 72;    // elems -> 144 B rows (144/16=9, odd)
constexpr int LDB = 136;   // elems -> 272 B rows (17, odd)
constexpr int LDSTG = 132; // fp32 staging stride

// 3-stage ring: per stage A(128x64), B(64x128) fp16
constexpr int A_BUF = BM * LDA * 2;   // 18432 B
constexpr int B_BUF = BK * LDB * 2;   // 17408 B
constexpr int ST_A = 0;
constexpr int ST_B = A_BUF;
constexpr int STAGE_B = A_BUF + B_BUF;   // 35840
constexpr int SMEM_BYTES = 3 * STAGE_B;  // 107520 (2 CTAs/SM)

__device__ __half g_X1[(size_t)ROWS_ALLOC * CH];
__device__ __half g_X2[(size_t)ROWS_ALLOC * CH];
__device__ __half g_W1T[(size_t)KDIM * CH];   // [kidx*CH+ic][oc]
__device__ __half g_W2T[(size_t)KDIM * C2];
__device__ float g_part[(size_t)SPLITS1 * NMT1 * 8 * BM * BN];
__device__ float g_pooled[NWIN * C2];
__device__ float g_m1[NWIN * 512];
__device__ float g_m2[NWIN * 512];

// conv2 valid-row index (all 32 slabs) -> padded row
__device__ __forceinline__ int padded_row2(int i) {
    int t = i / 784, rem = i - t * 784;
    int d = rem / 196, s = rem - d * 196;
    int h = s / 14, w = s - h * 14;
    return (t * WINSLABS + d + 1) * SLAB + (h + 1) * 16 + (w + 1);
}

// conv1 compacted-row index (25 nonzero slabs) -> padded row; dummy rows -> 273 (safe)
__device__ __forceinline__ int padded_row1(int i) {
    if (i >= VROWS1) return 273;
    int s = i / 196, pos = i - s * 196;
    int t, d;
    if (s < 2)      { t = 1; d = s + 2; }
    else if (s < 5) { t = 2; d = s - 1; }
    else            { int q = s - 5; t = 3 + (q >> 2); d = q & 3; }
    int h = pos / 14, w = pos - h * 14;
    return (t * WINSLABS + d + 1) * SLAB + (h + 1) * 16 + (w + 1);
}

__device__ __forceinline__ uint32_t smem_u32(const void* p) {
    uint32_t a;
    asm("{ .reg .u64 t; cvta.to.shared.u64 t, %1; cvt.u32.u64 %0, t; }" : "=r"(a) : "l"(p));
    return a;
}
#define CP_ASYNC16(dst, src) \
    asm volatile("cp.async.cg.shared.global [%0], [%1], 16;" :: "r"(dst), "l"(src))
#define CP_COMMIT() asm volatile("cp.async.commit_group;" ::: "memory")
#define CP_WAIT0()  asm volatile("cp.async.wait_group 0;" ::: "memory")
#define CP_WAIT1()  asm volatile("cp.async.wait_group 1;" ::: "memory")

// ---------------- prep kernels ----------------
__global__ void k_zero_pooled() {
    int i = blockIdx.x * 256 + threadIdx.x;
    if (i < NWIN * C2) g_pooled[i] = 0.f;
}

__global__ void k_gather(const float* __restrict__ videos) {
    int i = blockIdx.x * 256 + threadIdx.x;
    constexpr int TOT = NWIN * 4 * 14 * 14 * CH;
    if (i >= TOT) return;
    int c = i & (CH - 1);
    int rest = i >> 10;
    int w = rest % 14; rest /= 14;
    int h = rest % 14; rest /= 14;
    int d = rest & 3;
    int t = rest >> 2;
    int frame = t - 4 + d;  // window t holds frames t-4..t-1 (zeros before 0)
    float v = (frame >= 0) ? videos[(size_t)(frame * CH + c) * 196 + h * 14 + w] : 0.f;
    size_t dst = (size_t)(GUARD + (t * WINSLABS + d + 1) * SLAB + (h + 1) * 16 + (w + 1)) * CH + c;
    g_X1[dst] = __float2half(v);
}

// fill the 7 all-zero-input conv1 output slabs with relu(b1)
__global__ void k_fill(const float* __restrict__ b1) {
    int i = blockIdx.x * 256 + threadIdx.x;
    constexpr int TOT = 7 * 196 * CH;
    if (i >= TOT) return;
    int c = i & (CH - 1);
    int rest = i >> 10;
    int s2 = rest / 196, pos = rest - s2 * 196;
    int t = (s2 < 4) ? 0 : (s2 < 6) ? 1 : 2;
    int d = (s2 < 4) ? s2 : (s2 < 6) ? s2 - 4 : 0;
    int h = pos / 14, w = pos - h * 14;
    size_t o = (size_t)(GUARD + (t * WINSLABS + d + 1) * SLAB + (h + 1) * 16 + (w + 1)) * CH + c;
    g_X2[o] = __float2half(fmaxf(b1[c], 0.f));
}

// conv weights (oc, ic, 27) -> WT[kidx*CH+ic][oc], fp16
template<int NOC>
__global__ void k_transpose(const float* __restrict__ w, __half* __restrict__ wt) {
    __shared__ float s[32][28];
    int ocBase = blockIdx.x * 32;
    int ic = blockIdx.y;
    for (int idx = threadIdx.x; idx < 32 * 27; idx += 256) {
        int oc = idx / 27, kk = idx - oc * 27;
        s[oc][kk] = w[((size_t)(ocBase + oc) * CH + ic) * 27 + kk];
    }
    __syncthreads();
    for (int idx = threadIdx.x; idx < 27 * 32; idx += 256) {
        int kk = idx >> 5, oc = idx & 31;
        wt[((size_t)kk * CH + ic) * NOC + ocBase + oc] = __float2half(s[oc][kk]);
    }
}

// ---- implicit-conv GEMM: fp16, BK=64, 3-stage cp.async, frag double-buffer ----
template<int N, bool L2, int SPL, int NMT, int KCH>
__global__ void __launch_bounds__(256, 2)
k_gemm(int dummy) {
    const __half* __restrict__ X = (L2 ? g_X2 : g_X1) + (size_t)GUARD * CH;
    const __half* __restrict__ W = L2 ? g_W2T : g_W1T;
    constexpr int NB = N / BN;

    extern __shared__ __align__(128) char smem_raw[];
    const uint32_t sbase = smem_u32(smem_raw);

    const int tid = threadIdx.x;
    const int mtile = blockIdx.x;
    const int nBase = blockIdx.y * BN;
    const int split = blockIdx.z;
    const int k0 = split * KCH;

    // per-thread A source rows (4 rows, fixed across K loop)
    const int r0 = tid >> 3;          // 0..31
    long pr[4];
#pragma unroll
    for (int it = 0; it < 4; it++) {
        int gi = mtile * BM + r0 + it * 32;
        pr[it] = L2 ? padded_row2(gi) : padded_row1(gi);
    }
    const int ac = (tid & 7) * 8;     // A column elem offset within 64

    wmma::fragment<wmma::accumulator, 16, 16, 16, float> acc[4][2];
#pragma unroll
    for (int i = 0; i < 4; i++)
#pragma unroll
        for (int j = 0; j < 2; j++) wmma::fill_fragment(acc[i][j], 0.f);

    const int warpId = tid >> 5;
    const int warpM = warpId >> 2;
    const int warpN = warpId & 3;

    auto loadChunk = [&](int kt, int stage) {
        const int kidx = kt >> 4;             // tap 0..26
        const int icBase = (kt & 15) << 6;    // 64-ch block
        const int kd = kidx / 9, r9 = kidx - kd * 9;
        const int kh = r9 / 3, kw = r9 - kh * 3;
        const long off = (long)(kd - 1) * SLAB + (kh - 1) * 16 + (kw - 1);
        const uint32_t sb = sbase + stage * STAGE_B;
#pragma unroll
        for (int it = 0; it < 4; it++) {
            const long so = (pr[it] + off) * CH + icBase + ac;
            CP_ASYNC16(sb + ST_A + (r0 + it * 32) * (LDA * 2) + ac * 2, X + so);
        }
        const size_t wb = (size_t)kt * BK * N + nBase;
#pragma unroll
        for (int it = 0; it < 4; it++) {
            int v = it * 256 + tid;
            int row = v >> 4, c = v & 15;     // 64 rows x 16 segs
            CP_ASYNC16(sb + ST_B + row * (LDB * 2) + c * 16, W + wb + (size_t)row * N + c * 8);
        }
    };

    loadChunk(k0, 0);     CP_COMMIT();
    loadChunk(k0 + 1, 1); CP_COMMIT();

    wmma::fragment<wmma::matrix_a, 16, 16, 16, __half, wmma::row_major> fa[2][4];
    wmma::fragment<wmma::matrix_b, 16, 16, 16, __half, wmma::row_major> fb[2][2];

    int stage = 0, nstage = 2;
    for (int kk = 0; kk < KCH; kk++) {
        if (kk < KCH - 1) CP_WAIT1(); else CP_WAIT0();
        __syncthreads();
        if (kk + 2 < KCH) {
            loadChunk(k0 + kk + 2, nstage);
            CP_COMMIT();
        }
        const char* sb = smem_raw + stage * STAGE_B;
        const __half* aa = (const __half*)(sb + ST_A);
        const __half* bb = (const __half*)(sb + ST_B);

        // preload ks=0 fragments
#pragma unroll
        for (int j = 0; j < 2; j++)
            wmma::load_matrix_sync(fb[0][j], bb + warpN * 32 + j * 16, LDB);
#pragma unroll
        for (int i = 0; i < 4; i++)
            wmma::load_matrix_sync(fa[0][i], aa + (warpM * 64 + i * 16) * LDA, LDA);

#pragma unroll
        for (int ks = 0; ks < 4; ks++) {
            const int p = ks & 1;
            if (ks < 3) {   // prefetch ks+1 fragments into alternate set
#pragma unroll
                for (int j = 0; j < 2; j++)
                    wmma::load_matrix_sync(fb[p ^ 1][j],
                        bb + (ks + 1) * 16 * LDB + warpN * 32 + j * 16, LDB);
#pragma unroll
                for (int i = 0; i < 4; i++)
                    wmma::load_matrix_sync(fa[p ^ 1][i],
                        aa + (warpM * 64 + i * 16) * LDA + (ks + 1) * 16, LDA);
            }
#pragma unroll
            for (int i = 0; i < 4; i++)
#pragma unroll
                for (int j = 0; j < 2; j++)
                    wmma::mma_sync(acc[i][j], fa[p][i], fb[p][j], acc[i][j]);
        }
        stage = (stage + 1 == 3) ? 0 : stage + 1;
        nstage = (nstage + 1 == 3) ? 0 : nstage + 1;
    }
    __syncthreads();

    // stage + coalesced fp32 partial store (67584 B <= 107520)
    float* Stage = (float*)smem_raw;
#pragma unroll
    for (int i = 0; i < 4; i++)
#pragma unroll
        for (int j = 0; j < 2; j++)
            wmma::store_matrix_sync(Stage + (warpM * 64 + i * 16) * LDSTG + warpN * 32 + j * 16,
                                    acc[i][j], LDSTG, wmma::mem_row_major);
    __syncthreads();

    float* dst = g_part + ((size_t)(split * NMT + mtile) * NB + blockIdx.y) * (BM * BN);
#pragma unroll
    for (int it = 0; it < 16; it++) {
        int v = it * 256 + tid;
        int row = v >> 5, c4 = (v & 31) * 4;
        *(float4*)(dst + row * BN + c4) = *(const float4*)(Stage + row * LDSTG + c4);
    }
}

// conv1 epilogue: sum SPLITS1 partials + bias + relu -> X2 fp16 (skip dummy rows)
__global__ void k_epi1(const float* __restrict__ bias) {
    const int mtile = blockIdx.x, nblk = blockIdx.y;
    const int col = threadIdx.x & 127, rh = threadIdx.x >> 7;
    const size_t tile_sz = (size_t)BM * BN;
    const size_t tb = ((size_t)mtile * 8 + nblk) * tile_sz;
    const float b = bias[nblk * 128 + col];
    for (int rr = rh * 64; rr < rh * 64 + 64; rr++) {
        int gi = mtile * BM + rr;
        if (gi >= VROWS1) break;
        int e = rr * BN + col;
        float v = 0.f;
#pragma unroll
        for (int s = 0; s < SPLITS1; s++)
            v += g_part[(size_t)s * NMT1 * 8 * tile_sz + tb + e];
        v = fmaxf(v + b, 0.f);
        size_t o = (size_t)(GUARD + padded_row1(gi)) * CH + nblk * 128 + col;
        g_X2[o] = __float2half(v);
    }
}

// conv2 epilogue: sum SPLITS2 partials + bias + relu + maxpool -> g_pooled
__global__ void k_epi2(const float* __restrict__ bias) {
    const int mtile = blockIdx.x, nblk = blockIdx.y;
    const int col = threadIdx.x;  // 128 threads
    const size_t tile_sz = (size_t)BM * BN;
    const size_t tb = ((size_t)mtile * 4 + nblk) * tile_sz;
    const float* P0 = g_part + tb;
    const float* P1 = g_part + (size_t)NMT2 * 4 * tile_sz + tb;
    const float* P2 = g_part + (size_t)2 * NMT2 * 4 * tile_sz + tb;
    const float b = bias[nblk * 128 + col];
    float m = 0.f;
    int curt = (mtile * BM) / 784;
    for (int rr = 0; rr < BM; rr++) {
        int t = (mtile * BM + rr) / 784;
        if (t != curt) {
            atomicMax((int*)&g_pooled[curt * C2 + nblk * 128 + col], __float_as_int(m));
            m = 0.f;
            curt = t;
        }
        int e = rr * BN + col;
        m = fmaxf(m, P0[e] + P1[e] + P2[e] + b);
    }
    atomicMax((int*)&g_pooled[curt * C2 + nblk * 128 + col], __float_as_int(m));
}

// ---------------- tiny MLP ----------------
template<int IN, int OUT>
__global__ void k_fc(const float* __restrict__ W, const float* __restrict__ b,
                     const float* __restrict__ x, float* __restrict__ y) {
    int w = threadIdx.x >> 5, lane = threadIdx.x & 31;
    int o = blockIdx.x * 8 + w, t = blockIdx.y;
    float s = 0.f;
    for (int i = lane; i < IN; i += 32) s += x[t * IN + i] * W[(size_t)o * IN + i];
#pragma unroll
    for (int d = 16; d; d >>= 1) s += __shfl_down_sync(0xffffffffu, s, d);
    if (lane == 0) y[t * OUT + o] = fmaxf(s + b[o], 0.f);
}

extern "C" void kernel_launch(void* const* d_in, const int* in_sizes, int n_in,
                              void* d_out, int out_size) {
    const float* videos  = (const float*)d_in[0];
    const float* conv1_w = (const float*)d_in[1];
    const float* conv1_b = (const float*)d_in[2];
    const float* conv2_w = (const float*)d_in[3];
    const float* conv2_b = (const float*)d_in[4];
    const float* l1_w = (const float*)d_in[5];
    const float* l1_b = (const float*)d_in[6];
    const float* l2_w = (const float*)d_in[7];
    const float* l2_b = (const float*)d_in[8];
    const float* l3_w = (const float*)d_in[9];
    const float* l3_b = (const float*)d_in[10];
    float* out = (float*)d_out;

    auto g1 = k_gemm<CH, false, SPLITS1, NMT1, KCH1>;
    auto g2 = k_gemm<C2, true,  SPLITS2, NMT2, KCH2>;
    cudaFuncSetAttribute(g1, cudaFuncAttributeMaxDynamicSharedMemorySize, SMEM_BYTES);
    cudaFuncSetAttribute(g2, cudaFuncAttributeMaxDynamicSharedMemorySize, SMEM_BYTES);

    __half *w1t, *w2t;
    float *pooled, *m1, *m2;
    cudaGetSymbolAddress((void**)&w1t, g_W1T);
    cudaGetSymbolAddress((void**)&w2t, g_W2T);
    cudaGetSymbolAddress((void**)&pooled, g_pooled);
    cudaGetSymbolAddress((void**)&m1, g_m1);
    cudaGetSymbolAddress((void**)&m2, g_m2);

    constexpr int TOT = NWIN * 4 * 14 * 14 * CH;
    // g1 in the ncu-profiled slot (4th launch)
    k_gather<<<(TOT + 255) / 256, 256>>>(videos);
    k_transpose<CH><<<dim3(CH / 32, CH), 256>>>(conv1_w, w1t);
    k_zero_pooled<<<(NWIN * C2 + 255) / 256, 256>>>();

    g1<<<dim3(NMT1, CH / BN, SPLITS1), 256, SMEM_BYTES>>>(0);

    k_transpose<C2><<<dim3(C2 / 32, CH), 256>>>(conv2_w, w2t);
    k_fill<<<(7 * 196 * CH + 255) / 256, 256>>>(conv1_b);
    k_epi1<<<dim3(NMT1, CH / BN), 256>>>(conv1_b);

    g2<<<dim3(NMT2, C2 / BN, SPLITS2), 256, SMEM_BYTES>>>(0);
    k_epi2<<<dim3(NMT2, C2 / BN), 128>>>(conv2_b);

    k_fc<512, 512><<<dim3(64, NWIN), 256>>>(l1_w, l1_b, pooled, m1);
    k_fc<512, 512><<<dim3(64, NWIN), 256>>>(l2_w, l2_b, m1, m2);
    k_fc<512, 128><<<dim3(16, NWIN), 256>>>(l3_w, l3_b, m2, out);
}